// round 1
// baseline (speedup 1.0000x reference)
#include <cuda_runtime.h>
#include <cuda_bf16.h>
#include <math.h>

#define HIDDEN 1024
#define HEADS 16
#define HEADD 64
#define LAYERS 4
#define MLPD 4096
#define NTOK 1568
#define BATCH 2
#define ROWS (BATCH * NTOK)          // 3136
#define PATCH_K 1536                 // 3*2*16*16

// ---------------- scratch (device globals; no allocation allowed) ----------------
__device__ float g_h  [ROWS * HIDDEN];
__device__ float g_xn [ROWS * HIDDEN];
__device__ float g_q  [ROWS * HIDDEN];
__device__ float g_k  [ROWS * HIDDEN];
__device__ float g_v  [ROWS * HIDDEN];
__device__ float g_ao [ROWS * HIDDEN];
__device__ float g_mlp[ROWS * MLPD];
__device__ float g_col[ROWS * PATCH_K];

// ---------------- im2col for the tube conv (stride == kernel) ----------------
__global__ void im2col_k(const float* __restrict__ px, float* __restrict__ col) {
    int idx = blockIdx.x * 256 + threadIdx.x;
    if (idx >= ROWS * PATCH_K) return;
    int m = idx / PATCH_K;
    int j = idx - m * PATCH_K;
    // j = ((c*2 + t)*16 + ph)*16 + pw
    int c  = j >> 9;            // /512
    int r  = j & 511;
    int t  = r >> 8;            // /256
    int ph = (r >> 4) & 15;
    int pw = r & 15;
    int b = m / NTOK;
    int n = m - b * NTOK;
    int d  = n / 196;
    int rr = n - d * 196;
    int hy = rr / 14;
    int wx = rr - hy * 14;
    // px layout: (B, FRAMES=16, C=3, 224, 224)
    size_t src = ((size_t)((b * 16 + d * 2 + t) * 3 + c)) * (224 * 224)
               + (size_t)(hy * 16 + ph) * 224 + (wx * 16 + pw);
    col[idx] = px[src];
}

// ---------------- generic SGEMM: C[m,n] = sum_k A[m,k]*B[n,k] + bias[n] (+epilogue)
// MODE 0: bias, 1: bias+gelu(exact), 2: bias+residual
template <int MODE>
__global__ __launch_bounds__(256) void gemm_k(
    const float* __restrict__ A, const float* __restrict__ B,
    const float* __restrict__ bias, const float* __restrict__ res,
    float* __restrict__ C, int M, int N, int K)
{
    __shared__ float As[16][128];
    __shared__ float Bs[16][128];
    int tid = threadIdx.x;
    int m0 = blockIdx.y * 128;
    int n0 = blockIdx.x * 128;
    int tx = tid & 15, ty = tid >> 4;

    float acc[8][8];
#pragma unroll
    for (int i = 0; i < 8; i++)
#pragma unroll
        for (int j = 0; j < 8; j++) acc[i][j] = 0.f;

    for (int k0 = 0; k0 < K; k0 += 16) {
#pragma unroll
        for (int u = 0; u < 2; u++) {
            int idx = tid + u * 256;
            int r = idx >> 2, kq = idx & 3;
            int gm = m0 + r;
            float4 a = (gm < M) ? *(const float4*)&A[(size_t)gm * K + k0 + kq * 4]
                                : make_float4(0.f, 0.f, 0.f, 0.f);
            As[kq * 4 + 0][r] = a.x; As[kq * 4 + 1][r] = a.y;
            As[kq * 4 + 2][r] = a.z; As[kq * 4 + 3][r] = a.w;
            int gn = n0 + r;
            float4 bb = *(const float4*)&B[(size_t)gn * K + k0 + kq * 4];
            Bs[kq * 4 + 0][r] = bb.x; Bs[kq * 4 + 1][r] = bb.y;
            Bs[kq * 4 + 2][r] = bb.z; Bs[kq * 4 + 3][r] = bb.w;
        }
        __syncthreads();
#pragma unroll
        for (int kk = 0; kk < 16; kk++) {
            float ra[8], rb[8];
#pragma unroll
            for (int i = 0; i < 8; i++) ra[i] = As[kk][ty * 8 + i];
#pragma unroll
            for (int j = 0; j < 8; j++) rb[j] = Bs[kk][tx * 8 + j];
#pragma unroll
            for (int i = 0; i < 8; i++)
#pragma unroll
                for (int j = 0; j < 8; j++) acc[i][j] += ra[i] * rb[j];
        }
        __syncthreads();
    }

#pragma unroll
    for (int i = 0; i < 8; i++) {
        int gm = m0 + ty * 8 + i;
        if (gm >= M) continue;
#pragma unroll
        for (int j = 0; j < 8; j++) {
            int gn = n0 + tx * 8 + j;
            float v = acc[i][j] + bias[gn];
            if (MODE == 1) v = 0.5f * v * (1.f + erff(v * 0.70710678118654752f));
            if (MODE == 2) v += res[(size_t)gm * N + gn];
            C[(size_t)gm * N + gn] = v;
        }
    }
}

// ---------------- LayerNorm (one block per row of 1024) ----------------
__global__ __launch_bounds__(256) void ln_k(
    const float* __restrict__ x, const float* __restrict__ g,
    const float* __restrict__ b, float* __restrict__ y)
{
    __shared__ float red[8];
    __shared__ float stat[2];
    int row = blockIdx.x, tid = threadIdx.x;
    const float* xr = x + (size_t)row * HIDDEN;
    float v[4];
    float s = 0.f;
#pragma unroll
    for (int i = 0; i < 4; i++) { v[i] = xr[tid + i * 256]; s += v[i]; }
#pragma unroll
    for (int o = 16; o > 0; o >>= 1) s += __shfl_xor_sync(~0u, s, o);
    if ((tid & 31) == 0) red[tid >> 5] = s;
    __syncthreads();
    if (tid < 32) {
        float t = (tid < 8) ? red[tid] : 0.f;
#pragma unroll
        for (int o = 4; o > 0; o >>= 1) t += __shfl_xor_sync(~0u, t, o);
        if (tid == 0) stat[0] = t * (1.f / HIDDEN);
    }
    __syncthreads();
    float mu = stat[0];
    float s2 = 0.f;
#pragma unroll
    for (int i = 0; i < 4; i++) { float d = v[i] - mu; s2 += d * d; }
#pragma unroll
    for (int o = 16; o > 0; o >>= 1) s2 += __shfl_xor_sync(~0u, s2, o);
    if ((tid & 31) == 0) red[tid >> 5] = s2;
    __syncthreads();
    if (tid < 32) {
        float t = (tid < 8) ? red[tid] : 0.f;
#pragma unroll
        for (int o = 4; o > 0; o >>= 1) t += __shfl_xor_sync(~0u, t, o);
        if (tid == 0) stat[1] = rsqrtf(t * (1.f / HIDDEN) + 1e-6f);
    }
    __syncthreads();
    float rs = stat[1];
    float* yr = y + (size_t)row * HIDDEN;
#pragma unroll
    for (int i = 0; i < 4; i++) {
        int c = tid + i * 256;
        yr[c] = (v[i] - mu) * rs * g[c] + b[c];
    }
}

// ---------------- RoPE (VJEPA2: tiled sin/cos, interleaved rotate-half) ------
// For each head, dims [0,20) rotate with d_pos, [20,40) with h_pos, [40,60) with
// w_pos; dims [60,64) untouched. Pair (2i, 2i+1) inside a 20-chunk:
//   out[2i]   = x[2i]  *cos(f_{(2i)%10})   - x[2i+1]*sin(f_{(2i)%10})
//   out[2i+1] = x[2i+1]*cos(f_{(2i+1)%10}) + x[2i]  *sin(f_{(2i+1)%10})
// with f_i = pos * 10000^{-i/10}.
__global__ void rope_k(float* __restrict__ q, float* __restrict__ k) {
    int idx = blockIdx.x * 256 + threadIdx.x;
    const int TOTAL = ROWS * HEADS * 30;
    if (idx >= TOTAL) return;
    int pair = idx % 30;
    int t = idx / 30;
    int h = t & 15;
    int bn = t >> 4;            // 0..3135 (b*1568+n)
    int n = bn % NTOK;
    int a = pair / 10, i = pair - a * 10;
    int dpos = n / 196, r = n - dpos * 196;
    int pos = (a == 0) ? dpos : (a == 1) ? (r / 14) : (r % 14);
    int i0 = (2 * i) % 10, i1 = (2 * i + 1) % 10;
    const float LN1E4_O10 = 0.92103403719761840f;  // ln(10000)/10
    float f0 = (float)pos * expf(-LN1E4_O10 * (float)i0);
    float f1 = (float)pos * expf(-LN1E4_O10 * (float)i1);
    float s0, c0, s1, c1;
    sincosf(f0, &s0, &c0);
    sincosf(f1, &s1, &c1);
    size_t base = (size_t)bn * HIDDEN + h * HEADD + a * 20 + 2 * i;
    float q0 = q[base], q1 = q[base + 1];
    q[base]     = q0 * c0 - q1 * s0;
    q[base + 1] = q1 * c1 + q0 * s1;
    float k0 = k[base], k1 = k[base + 1];
    k[base]     = k0 * c0 - k1 * s0;
    k[base + 1] = k1 * c1 + k0 * s1;
}

// ---------------- Flash attention, fp32, 64-query tiles ----------------
// grid: (25 qtiles, 32 batch-heads). block 256 (8 warps x 8 queries each).
// Q/K/V layout: [b, n, h*64 + d] (row stride 1024).
#define ATTN_SMEM_FLOATS (4096 + 64 * 65 + 4096 + 4096)
__global__ __launch_bounds__(256) void attn_k(
    const float* __restrict__ Q, const float* __restrict__ K,
    const float* __restrict__ V, float* __restrict__ O)
{
    extern __shared__ float sm[];
    float* Qs  = sm;                 // [64][64]  q*64+d  (pre-scaled)
    float* Kst = sm + 4096;          // [64][65]  d*65+k  (transposed, padded)
    float* Vs  = Kst + 64 * 65;      // [64][64]  k*64+d
    float* Ss  = Vs + 4096;          // [64][64]  q*64+k

    int bh = blockIdx.y;
    int b = bh >> 4, h = bh & 15;
    int q0 = blockIdx.x * 64;
    int tid = threadIdx.x, warp = tid >> 5, lane = tid & 31;

    const float* Qb = Q + (size_t)b * NTOK * HIDDEN + h * HEADD;
    const float* Kb = K + (size_t)b * NTOK * HIDDEN + h * HEADD;
    const float* Vb = V + (size_t)b * NTOK * HIDDEN + h * HEADD;

#pragma unroll
    for (int i = 0; i < 16; i++) {
        int e = tid + i * 256;
        int r = e >> 6, c = e & 63;
        int qi = q0 + r;
        Qs[r * 64 + c] = (qi < NTOK) ? Qb[(size_t)qi * HIDDEN + c] * 0.125f : 0.f;
    }

    float m_i[8], l_i[8], acc0[8], acc1[8];
#pragma unroll
    for (int qq = 0; qq < 8; qq++) {
        m_i[qq] = -1e30f; l_i[qq] = 0.f; acc0[qq] = 0.f; acc1[qq] = 0.f;
    }

    for (int kt = 0; kt < 25; kt++) {
        int k0 = kt * 64;
        __syncthreads();  // prior iteration done with Kst/Vs
#pragma unroll
        for (int i = 0; i < 16; i++) {
            int e = tid + i * 256;
            int r = e >> 6, c = e & 63;
            int ki = k0 + r;
            float kv = (ki < NTOK) ? Kb[(size_t)ki * HIDDEN + c] : 0.f;
            float vv = (ki < NTOK) ? Vb[(size_t)ki * HIDDEN + c] : 0.f;
            Kst[c * 65 + r] = kv;
            Vs[r * 64 + c]  = vv;
        }
        __syncthreads();

        // S = Qtile . Ktile^T   (each lane: 2 key cols x 8 query rows)
        float sv0[8], sv1[8];
#pragma unroll
        for (int qq = 0; qq < 8; qq++) { sv0[qq] = 0.f; sv1[qq] = 0.f; }
#pragma unroll 8
        for (int d = 0; d < 64; d++) {
            float ka = Kst[d * 65 + lane];
            float kb2 = Kst[d * 65 + lane + 32];
#pragma unroll
            for (int qq = 0; qq < 8; qq++) {
                float qv = Qs[(warp * 8 + qq) * 64 + d];
                sv0[qq] += qv * ka;
                sv1[qq] += qv * kb2;
            }
        }
        bool val0 = (k0 + lane) < NTOK;
        bool val1 = (k0 + lane + 32) < NTOK;

        // online softmax per query row
#pragma unroll
        for (int qq = 0; qq < 8; qq++) {
            float s0 = val0 ? sv0[qq] : -1e30f;
            float s1 = val1 ? sv1[qq] : -1e30f;
            float mx = fmaxf(s0, s1);
#pragma unroll
            for (int o = 16; o > 0; o >>= 1) mx = fmaxf(mx, __shfl_xor_sync(~0u, mx, o));
            float mnew = fmaxf(m_i[qq], mx);
            float p0 = __expf(s0 - mnew);
            float p1 = __expf(s1 - mnew);
            float psum = p0 + p1;
#pragma unroll
            for (int o = 16; o > 0; o >>= 1) psum += __shfl_xor_sync(~0u, psum, o);
            float corr = __expf(m_i[qq] - mnew);
            l_i[qq] = l_i[qq] * corr + psum;
            m_i[qq] = mnew;
            acc0[qq] *= corr;
            acc1[qq] *= corr;
            Ss[(warp * 8 + qq) * 64 + lane] = p0;
            Ss[(warp * 8 + qq) * 64 + lane + 32] = p1;
        }
        __syncwarp();

        // O += P . V   (lane owns dims lane and lane+32)
#pragma unroll 8
        for (int kk = 0; kk < 64; kk++) {
            float va = Vs[kk * 64 + lane];
            float vb2 = Vs[kk * 64 + lane + 32];
#pragma unroll
            for (int qq = 0; qq < 8; qq++) {
                float p = Ss[(warp * 8 + qq) * 64 + kk];
                acc0[qq] += p * va;
                acc1[qq] += p * vb2;
            }
        }
    }

    float* Ob = O + (size_t)b * NTOK * HIDDEN + h * HEADD;
#pragma unroll
    for (int qq = 0; qq < 8; qq++) {
        int qi = q0 + warp * 8 + qq;
        if (qi >= NTOK) continue;
        float inv = 1.f / l_i[qq];
        Ob[(size_t)qi * HIDDEN + lane]      = acc0[qq] * inv;
        Ob[(size_t)qi * HIDDEN + lane + 32] = acc1[qq] * inv;
    }
}

// ---------------- host orchestration ----------------
extern "C" void kernel_launch(void* const* d_in, const int* in_sizes, int n_in,
                              void* d_out, int out_size) {
    (void)in_sizes; (void)n_in; (void)out_size;
    const float* px      = (const float*)d_in[0];
    const float* patch_w = (const float*)d_in[1];
    const float* patch_b = (const float*)d_in[2];
    const float* ln1g = (const float*)d_in[3];
    const float* ln1b = (const float*)d_in[4];
    const float* qw = (const float*)d_in[5];
    const float* qb = (const float*)d_in[6];
    const float* kw = (const float*)d_in[7];
    const float* kb = (const float*)d_in[8];
    const float* vw = (const float*)d_in[9];
    const float* vb = (const float*)d_in[10];
    const float* pw = (const float*)d_in[11];
    const float* pb = (const float*)d_in[12];
    const float* ln2g = (const float*)d_in[13];
    const float* ln2b = (const float*)d_in[14];
    const float* fc1w = (const float*)d_in[15];
    const float* fc1b = (const float*)d_in[16];
    const float* fc2w = (const float*)d_in[17];
    const float* fc2b = (const float*)d_in[18];
    const float* lnfg = (const float*)d_in[19];
    const float* lnfb = (const float*)d_in[20];
    float* out = (float*)d_out;

    void *ph, *pxn, *pq, *pk, *pv, *pao, *pmlp, *pcol;
    cudaGetSymbolAddress(&ph,  g_h);
    cudaGetSymbolAddress(&pxn, g_xn);
    cudaGetSymbolAddress(&pq,  g_q);
    cudaGetSymbolAddress(&pk,  g_k);
    cudaGetSymbolAddress(&pv,  g_v);
    cudaGetSymbolAddress(&pao, g_ao);
    cudaGetSymbolAddress(&pmlp, g_mlp);
    cudaGetSymbolAddress(&pcol, g_col);
    float* h   = (float*)ph;
    float* xn  = (float*)pxn;
    float* q   = (float*)pq;
    float* k   = (float*)pk;
    float* v   = (float*)pv;
    float* ao  = (float*)pao;
    float* mlp = (float*)pmlp;
    float* col = (float*)pcol;

    const int ATTN_SMEM = ATTN_SMEM_FLOATS * 4;
    cudaFuncSetAttribute(attn_k, cudaFuncAttributeMaxDynamicSharedMemorySize, ATTN_SMEM);

    // patch embed
    im2col_k<<<(ROWS * PATCH_K + 255) / 256, 256>>>(px, col);
    gemm_k<0><<<dim3(HIDDEN / 128, 25), 256>>>(col, patch_w, patch_b, nullptr, h,
                                               ROWS, HIDDEN, PATCH_K);

    for (int l = 0; l < LAYERS; l++) {
        size_t wo = (size_t)l * HIDDEN * HIDDEN;
        size_t bo = (size_t)l * HIDDEN;
        // attention block
        ln_k<<<ROWS, 256>>>(h, ln1g + bo, ln1b + bo, xn);
        gemm_k<0><<<dim3(8, 25), 256>>>(xn, qw + wo, qb + bo, nullptr, q, ROWS, HIDDEN, HIDDEN);
        gemm_k<0><<<dim3(8, 25), 256>>>(xn, kw + wo, kb + bo, nullptr, k, ROWS, HIDDEN, HIDDEN);
        gemm_k<0><<<dim3(8, 25), 256>>>(xn, vw + wo, vb + bo, nullptr, v, ROWS, HIDDEN, HIDDEN);
        rope_k<<<(ROWS * HEADS * 30 + 255) / 256, 256>>>(q, k);
        attn_k<<<dim3(25, BATCH * HEADS), 256, ATTN_SMEM>>>(q, k, v, ao);
        gemm_k<2><<<dim3(8, 25), 256>>>(ao, pw + wo, pb + bo, h, h, ROWS, HIDDEN, HIDDEN);
        // MLP block
        ln_k<<<ROWS, 256>>>(h, ln2g + bo, ln2b + bo, xn);
        gemm_k<1><<<dim3(MLPD / 128, 25), 256>>>(xn, fc1w + (size_t)l * MLPD * HIDDEN,
                                                 fc1b + (size_t)l * MLPD, nullptr, mlp,
                                                 ROWS, MLPD, HIDDEN);
        gemm_k<2><<<dim3(8, 25), 256>>>(mlp, fc2w + (size_t)l * HIDDEN * MLPD,
                                        fc2b + bo, h, h, ROWS, HIDDEN, MLPD);
    }

    ln_k<<<ROWS, 256>>>(h, lnfg, lnfb, out);
}

// round 2
// speedup vs baseline: 2.1270x; 2.1270x over previous
#include <cuda_runtime.h>
#include <cuda_bf16.h>
#include <math.h>
#include <stdint.h>

#define HIDDEN 1024
#define HEADS 16
#define HEADD 64
#define LAYERS 4
#define MLPD 4096
#define NTOK 1568
#define BATCH 2
#define ROWS (BATCH * NTOK)          // 3136
#define PATCH_K 1536                 // 3*2*16*16

// ---------------- scratch (device globals; no allocation allowed) ----------------
__device__ float g_h  [ROWS * HIDDEN];
__device__ float g_xn [ROWS * HIDDEN];
__device__ float g_q  [ROWS * HIDDEN];
__device__ float g_k  [ROWS * HIDDEN];
__device__ float g_v  [ROWS * HIDDEN];
__device__ float g_ao [ROWS * HIDDEN];
__device__ float g_mlp[ROWS * MLPD];
__device__ float g_col[ROWS * PATCH_K];

// ---------------- im2col for the tube conv (stride == kernel) ----------------
__global__ void im2col_k(const float* __restrict__ px, float* __restrict__ col) {
    int idx = blockIdx.x * 256 + threadIdx.x;
    if (idx >= ROWS * PATCH_K) return;
    int m = idx / PATCH_K;
    int j = idx - m * PATCH_K;
    int c  = j >> 9;
    int r  = j & 511;
    int t  = r >> 8;
    int ph = (r >> 4) & 15;
    int pw = r & 15;
    int b = m / NTOK;
    int n = m - b * NTOK;
    int d  = n / 196;
    int rr = n - d * 196;
    int hy = rr / 14;
    int wx = rr - hy * 14;
    size_t src = ((size_t)((b * 16 + d * 2 + t) * 3 + c)) * (224 * 224)
               + (size_t)(hy * 16 + ph) * 224 + (wx * 16 + pw);
    col[idx] = px[src];
}

// ---------------- tf32 tensor-core GEMM ----------------
// C[m,n] = sum_k A[m,k]*B[n,k] + bias[n] (+epilogue)
// MODE 0: bias, 1: bias+gelu(exact), 2: bias+residual, 3: fused QKV (3 B/bias/C sets)
__device__ __forceinline__ uint32_t f2tf(float x) {
    uint32_t u;
    asm("cvt.rna.tf32.f32 %0, %1;" : "=r"(u) : "f"(x));
    return u;
}
__device__ __forceinline__ void mma8(float* c, uint32_t a0, uint32_t a1, uint32_t a2,
                                     uint32_t a3, uint32_t b0, uint32_t b1) {
    asm volatile(
        "mma.sync.aligned.m16n8k8.row.col.f32.tf32.tf32.f32 "
        "{%0,%1,%2,%3},{%4,%5,%6,%7},{%8,%9},{%0,%1,%2,%3};"
        : "+f"(c[0]), "+f"(c[1]), "+f"(c[2]), "+f"(c[3])
        : "r"(a0), "r"(a1), "r"(a2), "r"(a3), "r"(b0), "r"(b1));
}

// smem layout per buffer (A or B): 4 k-groups of 8, each group 128 rows x 4 "pairs"
// (pair = tf32 values for k and k+4, consecutive uint32). Group stride padded to
// 513 pairs to avoid store-side bank conflicts. 1 buffer = 4*513 pairs = 4104 u32.
#define GRP_PAIRS 513
#define BUF_U32   (4 * GRP_PAIRS * 2)        // 4104
#define DBUF_U32  (2 * BUF_U32)              // A+B per stage: 8208
#define GEMM_SMEM (2 * DBUF_U32 * 4)         // bytes: 65664

template <int MODE>
__global__ __launch_bounds__(256) void tgemm(
    const float* __restrict__ A,
    const float* __restrict__ B0, const float* __restrict__ B1, const float* __restrict__ B2,
    const float* __restrict__ bias0, const float* __restrict__ bias1, const float* __restrict__ bias2,
    const float* __restrict__ res, float* __restrict__ C0, float* __restrict__ C1,
    float* __restrict__ C2, int M, int N, int K)
{
    extern __shared__ uint32_t smu[];
    int m0 = blockIdx.y * 128;
    int n0 = blockIdx.x * 128;
    const float* B = B0;
    const float* bias = bias0;
    float* C = C0;
    if (MODE == 3) {
        int ws = n0 >> 10;
        if (ws == 1) { B = B1; bias = bias1; C = C1; }
        else if (ws == 2) { B = B2; bias = bias2; C = C2; }
        n0 &= 1023;
    }

    const int t = threadIdx.x;
    const int quad = t & 7;          // which k-quad (4 k's) of the 32-k chunk
    const int rbase = t >> 3;        // 0..31
    const int g8l = quad >> 1;       // k-group 0..3
    const int half = quad & 1;       // lo/hi half of pair
    const int warp = t >> 5, lane = t & 31;
    const int wm = (warp >> 2) * 64, wn = (warp & 3) * 32;
    const int g = lane >> 2, tig = lane & 3;

    float acc[4][4][4];
#pragma unroll
    for (int i = 0; i < 4; i++)
#pragma unroll
        for (int j = 0; j < 4; j++)
#pragma unroll
            for (int q = 0; q < 4; q++) acc[i][j][q] = 0.f;

    float4 ra[4], rb[4];
    const int NC = K >> 5;

    // prologue: load + store chunk 0
#pragma unroll
    for (int p = 0; p < 4; p++) {
        int gm = m0 + p * 32 + rbase;
        ra[p] = (gm < M) ? *(const float4*)&A[(size_t)gm * K + quad * 4]
                         : make_float4(0.f, 0.f, 0.f, 0.f);
        int gn = n0 + p * 32 + rbase;
        rb[p] = *(const float4*)&B[(size_t)gn * K + quad * 4];
    }
    {
        uint32_t* da = smu + g8l * (GRP_PAIRS * 2) + half;
        uint32_t* db = da + BUF_U32;
#pragma unroll
        for (int p = 0; p < 4; p++) {
            uint32_t* d = da + (p * 32 + rbase) * 8;
            d[0] = f2tf(ra[p].x); d[2] = f2tf(ra[p].y);
            d[4] = f2tf(ra[p].z); d[6] = f2tf(ra[p].w);
            uint32_t* e = db + (p * 32 + rbase) * 8;
            e[0] = f2tf(rb[p].x); e[2] = f2tf(rb[p].y);
            e[4] = f2tf(rb[p].z); e[6] = f2tf(rb[p].w);
        }
    }
    __syncthreads();

    for (int c = 0; c < NC; c++) {
        if (c + 1 < NC) {
            int k0n = (c + 1) << 5;
#pragma unroll
            for (int p = 0; p < 4; p++) {
                int gm = m0 + p * 32 + rbase;
                ra[p] = (gm < M) ? *(const float4*)&A[(size_t)gm * K + k0n + quad * 4]
                                 : make_float4(0.f, 0.f, 0.f, 0.f);
                int gn = n0 + p * 32 + rbase;
                rb[p] = *(const float4*)&B[(size_t)gn * K + k0n + quad * 4];
            }
        }
        const uint32_t* a = smu + (c & 1) * DBUF_U32;
        const uint32_t* bsh = a + BUF_U32;
#pragma unroll
        for (int gg = 0; gg < 4; gg++) {
            uint2 pa[4][2];
            uint2 pb[4];
#pragma unroll
            for (int fm = 0; fm < 4; fm++) {
                int r = wm + fm * 16 + g;
                pa[fm][0] = *(const uint2*)&a[(gg * GRP_PAIRS + r * 4 + tig) * 2];
                pa[fm][1] = *(const uint2*)&a[(gg * GRP_PAIRS + (r + 8) * 4 + tig) * 2];
            }
#pragma unroll
            for (int fn = 0; fn < 4; fn++) {
                int ci = wn + fn * 8 + g;
                pb[fn] = *(const uint2*)&bsh[(gg * GRP_PAIRS + ci * 4 + tig) * 2];
            }
#pragma unroll
            for (int fm = 0; fm < 4; fm++)
#pragma unroll
                for (int fn = 0; fn < 4; fn++)
                    mma8(acc[fm][fn], pa[fm][0].x, pa[fm][1].x, pa[fm][0].y, pa[fm][1].y,
                         pb[fn].x, pb[fn].y);
        }
        if (c + 1 < NC) {
            uint32_t* da = smu + ((c + 1) & 1) * DBUF_U32 + g8l * (GRP_PAIRS * 2) + half;
            uint32_t* db = da + BUF_U32;
#pragma unroll
            for (int p = 0; p < 4; p++) {
                uint32_t* d = da + (p * 32 + rbase) * 8;
                d[0] = f2tf(ra[p].x); d[2] = f2tf(ra[p].y);
                d[4] = f2tf(ra[p].z); d[6] = f2tf(ra[p].w);
                uint32_t* e = db + (p * 32 + rbase) * 8;
                e[0] = f2tf(rb[p].x); e[2] = f2tf(rb[p].y);
                e[4] = f2tf(rb[p].z); e[6] = f2tf(rb[p].w);
            }
        }
        __syncthreads();
    }

    // epilogue
#pragma unroll
    for (int fm = 0; fm < 4; fm++) {
        int r0 = m0 + wm + fm * 16 + g;
#pragma unroll
        for (int fn = 0; fn < 4; fn++) {
            int col = n0 + wn + fn * 8 + 2 * tig;
            float b0v = bias[col], b1v = bias[col + 1];
#pragma unroll
            for (int hrow = 0; hrow < 2; hrow++) {
                int r = r0 + hrow * 8;
                if (r >= M) continue;
                float v0 = acc[fm][fn][hrow * 2 + 0] + b0v;
                float v1 = acc[fm][fn][hrow * 2 + 1] + b1v;
                if (MODE == 1) {
                    v0 = 0.5f * v0 * (1.f + erff(v0 * 0.70710678118654752f));
                    v1 = 0.5f * v1 * (1.f + erff(v1 * 0.70710678118654752f));
                }
                if (MODE == 2) {
                    const float* rr = &res[(size_t)r * N + col];
                    v0 += rr[0]; v1 += rr[1];
                }
                *(float2*)&C[(size_t)r * N + col] = make_float2(v0, v1);
            }
        }
    }
}

// ---------------- LayerNorm (one block per row of 1024) ----------------
__global__ __launch_bounds__(256) void ln_k(
    const float* __restrict__ x, const float* __restrict__ g,
    const float* __restrict__ b, float* __restrict__ y)
{
    __shared__ float red[8];
    __shared__ float stat[2];
    int row = blockIdx.x, tid = threadIdx.x;
    const float* xr = x + (size_t)row * HIDDEN;
    float v[4];
    float s = 0.f;
#pragma unroll
    for (int i = 0; i < 4; i++) { v[i] = xr[tid + i * 256]; s += v[i]; }
#pragma unroll
    for (int o = 16; o > 0; o >>= 1) s += __shfl_xor_sync(~0u, s, o);
    if ((tid & 31) == 0) red[tid >> 5] = s;
    __syncthreads();
    if (tid < 32) {
        float t = (tid < 8) ? red[tid] : 0.f;
#pragma unroll
        for (int o = 4; o > 0; o >>= 1) t += __shfl_xor_sync(~0u, t, o);
        if (tid == 0) stat[0] = t * (1.f / HIDDEN);
    }
    __syncthreads();
    float mu = stat[0];
    float s2 = 0.f;
#pragma unroll
    for (int i = 0; i < 4; i++) { float d = v[i] - mu; s2 += d * d; }
#pragma unroll
    for (int o = 16; o > 0; o >>= 1) s2 += __shfl_xor_sync(~0u, s2, o);
    if ((tid & 31) == 0) red[tid >> 5] = s2;
    __syncthreads();
    if (tid < 32) {
        float t = (tid < 8) ? red[tid] : 0.f;
#pragma unroll
        for (int o = 4; o > 0; o >>= 1) t += __shfl_xor_sync(~0u, t, o);
        if (tid == 0) stat[1] = rsqrtf(t * (1.f / HIDDEN) + 1e-6f);
    }
    __syncthreads();
    float rs = stat[1];
    float* yr = y + (size_t)row * HIDDEN;
#pragma unroll
    for (int i = 0; i < 4; i++) {
        int c = tid + i * 256;
        yr[c] = (v[i] - mu) * rs * g[c] + b[c];
    }
}

// ---------------- RoPE (VJEPA2: tiled sin/cos, interleaved rotate-half) ------
__global__ void rope_k(float* __restrict__ q, float* __restrict__ k) {
    int idx = blockIdx.x * 256 + threadIdx.x;
    const int TOTAL = ROWS * HEADS * 30;
    if (idx >= TOTAL) return;
    int pair = idx % 30;
    int t = idx / 30;
    int h = t & 15;
    int bn = t >> 4;
    int n = bn % NTOK;
    int a = pair / 10, i = pair - a * 10;
    int dpos = n / 196, r = n - dpos * 196;
    int pos = (a == 0) ? dpos : (a == 1) ? (r / 14) : (r % 14);
    int i0 = (2 * i) % 10, i1 = (2 * i + 1) % 10;
    const float LN1E4_O10 = 0.92103403719761840f;
    float f0 = (float)pos * expf(-LN1E4_O10 * (float)i0);
    float f1 = (float)pos * expf(-LN1E4_O10 * (float)i1);
    float s0, c0, s1, c1;
    sincosf(f0, &s0, &c0);
    sincosf(f1, &s1, &c1);
    size_t base = (size_t)bn * HIDDEN + h * HEADD + a * 20 + 2 * i;
    float q0 = q[base], q1 = q[base + 1];
    q[base]     = q0 * c0 - q1 * s0;
    q[base + 1] = q1 * c1 + q0 * s1;
    float k0 = k[base], k1 = k[base + 1];
    k[base]     = k0 * c0 - k1 * s0;
    k[base + 1] = k1 * c1 + k0 * s1;
}

// ---------------- Flash attention, fp32, 64-query tiles ----------------
#define ATTN_SMEM_FLOATS (4096 + 64 * 65 + 4096 + 4096)
__global__ __launch_bounds__(256) void attn_k(
    const float* __restrict__ Q, const float* __restrict__ K,
    const float* __restrict__ V, float* __restrict__ O)
{
    extern __shared__ float sm[];
    float* Qs  = sm;
    float* Kst = sm + 4096;
    float* Vs  = Kst + 64 * 65;
    float* Ss  = Vs + 4096;

    int bh = blockIdx.y;
    int b = bh >> 4, h = bh & 15;
    int q0 = blockIdx.x * 64;
    int tid = threadIdx.x, warp = tid >> 5, lane = tid & 31;

    const float* Qb = Q + (size_t)b * NTOK * HIDDEN + h * HEADD;
    const float* Kb = K + (size_t)b * NTOK * HIDDEN + h * HEADD;
    const float* Vb = V + (size_t)b * NTOK * HIDDEN + h * HEADD;

#pragma unroll
    for (int i = 0; i < 16; i++) {
        int e = tid + i * 256;
        int r = e >> 6, c = e & 63;
        int qi = q0 + r;
        Qs[r * 64 + c] = (qi < NTOK) ? Qb[(size_t)qi * HIDDEN + c] * 0.125f : 0.f;
    }

    float m_i[8], l_i[8], acc0[8], acc1[8];
#pragma unroll
    for (int qq = 0; qq < 8; qq++) {
        m_i[qq] = -1e30f; l_i[qq] = 0.f; acc0[qq] = 0.f; acc1[qq] = 0.f;
    }

    for (int kt = 0; kt < 25; kt++) {
        int k0 = kt * 64;
        __syncthreads();
#pragma unroll
        for (int i = 0; i < 16; i++) {
            int e = tid + i * 256;
            int r = e >> 6, c = e & 63;
            int ki = k0 + r;
            float kv = (ki < NTOK) ? Kb[(size_t)ki * HIDDEN + c] : 0.f;
            float vv = (ki < NTOK) ? Vb[(size_t)ki * HIDDEN + c] : 0.f;
            Kst[c * 65 + r] = kv;
            Vs[r * 64 + c]  = vv;
        }
        __syncthreads();

        float sv0[8], sv1[8];
#pragma unroll
        for (int qq = 0; qq < 8; qq++) { sv0[qq] = 0.f; sv1[qq] = 0.f; }
#pragma unroll 8
        for (int d = 0; d < 64; d++) {
            float ka = Kst[d * 65 + lane];
            float kb2 = Kst[d * 65 + lane + 32];
#pragma unroll
            for (int qq = 0; qq < 8; qq++) {
                float qv = Qs[(warp * 8 + qq) * 64 + d];
                sv0[qq] += qv * ka;
                sv1[qq] += qv * kb2;
            }
        }
        bool val0 = (k0 + lane) < NTOK;
        bool val1 = (k0 + lane + 32) < NTOK;

#pragma unroll
        for (int qq = 0; qq < 8; qq++) {
            float s0 = val0 ? sv0[qq] : -1e30f;
            float s1 = val1 ? sv1[qq] : -1e30f;
            float mx = fmaxf(s0, s1);
#pragma unroll
            for (int o = 16; o > 0; o >>= 1) mx = fmaxf(mx, __shfl_xor_sync(~0u, mx, o));
            float mnew = fmaxf(m_i[qq], mx);
            float p0 = __expf(s0 - mnew);
            float p1 = __expf(s1 - mnew);
            float psum = p0 + p1;
#pragma unroll
            for (int o = 16; o > 0; o >>= 1) psum += __shfl_xor_sync(~0u, psum, o);
            float corr = __expf(m_i[qq] - mnew);
            l_i[qq] = l_i[qq] * corr + psum;
            m_i[qq] = mnew;
            acc0[qq] *= corr;
            acc1[qq] *= corr;
            Ss[(warp * 8 + qq) * 64 + lane] = p0;
            Ss[(warp * 8 + qq) * 64 + lane + 32] = p1;
        }
        __syncwarp();

#pragma unroll 8
        for (int kk = 0; kk < 64; kk++) {
            float va = Vs[kk * 64 + lane];
            float vb2 = Vs[kk * 64 + lane + 32];
#pragma unroll
            for (int qq = 0; qq < 8; qq++) {
                float p = Ss[(warp * 8 + qq) * 64 + kk];
                acc0[qq] += p * va;
                acc1[qq] += p * vb2;
            }
        }
    }

    float* Ob = O + (size_t)b * NTOK * HIDDEN + h * HEADD;
#pragma unroll
    for (int qq = 0; qq < 8; qq++) {
        int qi = q0 + warp * 8 + qq;
        if (qi >= NTOK) continue;
        float inv = 1.f / l_i[qq];
        Ob[(size_t)qi * HIDDEN + lane]      = acc0[qq] * inv;
        Ob[(size_t)qi * HIDDEN + lane + 32] = acc1[qq] * inv;
    }
}

// ---------------- host orchestration ----------------
extern "C" void kernel_launch(void* const* d_in, const int* in_sizes, int n_in,
                              void* d_out, int out_size) {
    (void)in_sizes; (void)n_in; (void)out_size;
    const float* px      = (const float*)d_in[0];
    const float* patch_w = (const float*)d_in[1];
    const float* patch_b = (const float*)d_in[2];
    const float* ln1g = (const float*)d_in[3];
    const float* ln1b = (const float*)d_in[4];
    const float* qw = (const float*)d_in[5];
    const float* qb = (const float*)d_in[6];
    const float* kw = (const float*)d_in[7];
    const float* kb = (const float*)d_in[8];
    const float* vw = (const float*)d_in[9];
    const float* vb = (const float*)d_in[10];
    const float* pw = (const float*)d_in[11];
    const float* pb = (const float*)d_in[12];
    const float* ln2g = (const float*)d_in[13];
    const float* ln2b = (const float*)d_in[14];
    const float* fc1w = (const float*)d_in[15];
    const float* fc1b = (const float*)d_in[16];
    const float* fc2w = (const float*)d_in[17];
    const float* fc2b = (const float*)d_in[18];
    const float* lnfg = (const float*)d_in[19];
    const float* lnfb = (const float*)d_in[20];
    float* out = (float*)d_out;

    void *ph, *pxn, *pq, *pk, *pv, *pao, *pmlp, *pcol;
    cudaGetSymbolAddress(&ph,  g_h);
    cudaGetSymbolAddress(&pxn, g_xn);
    cudaGetSymbolAddress(&pq,  g_q);
    cudaGetSymbolAddress(&pk,  g_k);
    cudaGetSymbolAddress(&pv,  g_v);
    cudaGetSymbolAddress(&pao, g_ao);
    cudaGetSymbolAddress(&pmlp, g_mlp);
    cudaGetSymbolAddress(&pcol, g_col);
    float* h   = (float*)ph;
    float* xn  = (float*)pxn;
    float* q   = (float*)pq;
    float* k   = (float*)pk;
    float* v   = (float*)pv;
    float* ao  = (float*)pao;
    float* mlp = (float*)pmlp;
    float* col = (float*)pcol;

    const int ATTN_SMEM = ATTN_SMEM_FLOATS * 4;
    cudaFuncSetAttribute(attn_k, cudaFuncAttributeMaxDynamicSharedMemorySize, ATTN_SMEM);
    cudaFuncSetAttribute(tgemm<0>, cudaFuncAttributeMaxDynamicSharedMemorySize, GEMM_SMEM);
    cudaFuncSetAttribute(tgemm<1>, cudaFuncAttributeMaxDynamicSharedMemorySize, GEMM_SMEM);
    cudaFuncSetAttribute(tgemm<2>, cudaFuncAttributeMaxDynamicSharedMemorySize, GEMM_SMEM);
    cudaFuncSetAttribute(tgemm<3>, cudaFuncAttributeMaxDynamicSharedMemorySize, GEMM_SMEM);

    // patch embed
    im2col_k<<<(ROWS * PATCH_K + 255) / 256, 256>>>(px, col);
    tgemm<0><<<dim3(HIDDEN / 128, 25), 256, GEMM_SMEM>>>(
        col, patch_w, patch_w, patch_w, patch_b, patch_b, patch_b,
        nullptr, h, h, h, ROWS, HIDDEN, PATCH_K);

    for (int l = 0; l < LAYERS; l++) {
        size_t wo = (size_t)l * HIDDEN * HIDDEN;
        size_t bo = (size_t)l * HIDDEN;
        // attention block
        ln_k<<<ROWS, 256>>>(h, ln1g + bo, ln1b + bo, xn);
        tgemm<3><<<dim3(24, 25), 256, GEMM_SMEM>>>(
            xn, qw + wo, kw + wo, vw + wo, qb + bo, kb + bo, vb + bo,
            nullptr, q, k, v, ROWS, HIDDEN, HIDDEN);
        rope_k<<<(ROWS * HEADS * 30 + 255) / 256, 256>>>(q, k);
        attn_k<<<dim3(25, BATCH * HEADS), 256, ATTN_SMEM>>>(q, k, v, ao);
        tgemm<2><<<dim3(8, 25), 256, GEMM_SMEM>>>(
            ao, pw + wo, pw + wo, pw + wo, pb + bo, pb + bo, pb + bo,
            h, h, h, h, ROWS, HIDDEN, HIDDEN);
        // MLP block
        ln_k<<<ROWS, 256>>>(h, ln2g + bo, ln2b + bo, xn);
        tgemm<1><<<dim3(MLPD / 128, 25), 256, GEMM_SMEM>>>(
            xn, fc1w + (size_t)l * MLPD * HIDDEN, fc1w, fc1w,
            fc1b + (size_t)l * MLPD, fc1b, fc1b,
            nullptr, mlp, mlp, mlp, ROWS, MLPD, HIDDEN);
        tgemm<2><<<dim3(8, 25), 256, GEMM_SMEM>>>(
            mlp, fc2w + (size_t)l * HIDDEN * MLPD, fc2w, fc2w,
            fc2b + bo, fc2b, fc2b,
            h, h, h, h, ROWS, HIDDEN, MLPD);
    }

    ln_k<<<ROWS, 256>>>(h, lnfg, lnfb, out);
}

// round 3
// speedup vs baseline: 3.0926x; 1.4540x over previous
#include <cuda_runtime.h>
#include <cuda_bf16.h>
#include <math.h>
#include <stdint.h>

#define HIDDEN 1024
#define HEADS 16
#define HEADD 64
#define LAYERS 4
#define MLPD 4096
#define NTOK 1568
#define BATCH 2
#define ROWS (BATCH * NTOK)          // 3136
#define PATCH_K 1536                 // 3*2*16*16

// ---------------- scratch (device globals; no allocation allowed) ----------------
__device__ float g_h  [ROWS * HIDDEN];
__device__ float g_xn [ROWS * HIDDEN];
__device__ float g_q  [ROWS * HIDDEN];
__device__ float g_k  [ROWS * HIDDEN];
__device__ float g_v  [ROWS * HIDDEN];
__device__ float g_ao [ROWS * HIDDEN];
__device__ float g_mlp[ROWS * MLPD];
__device__ float g_col[ROWS * PATCH_K];

// ---------------- im2col for the tube conv (stride == kernel) ----------------
__global__ void im2col_k(const float* __restrict__ px, float* __restrict__ col) {
    int idx = blockIdx.x * 256 + threadIdx.x;
    if (idx >= ROWS * PATCH_K) return;
    int m = idx / PATCH_K;
    int j = idx - m * PATCH_K;
    int c  = j >> 9;
    int r  = j & 511;
    int t  = r >> 8;
    int ph = (r >> 4) & 15;
    int pw = r & 15;
    int b = m / NTOK;
    int n = m - b * NTOK;
    int d  = n / 196;
    int rr = n - d * 196;
    int hy = rr / 14;
    int wx = rr - hy * 14;
    size_t src = ((size_t)((b * 16 + d * 2 + t) * 3 + c)) * (224 * 224)
               + (size_t)(hy * 16 + ph) * 224 + (wx * 16 + pw);
    col[idx] = px[src];
}

// ---------------- tf32 helpers ----------------
__device__ __forceinline__ uint32_t f2tf(float x) {
    uint32_t u;
    asm("cvt.rna.tf32.f32 %0, %1;" : "=r"(u) : "f"(x));
    return u;
}
__device__ __forceinline__ void mma8(float* c, uint32_t a0, uint32_t a1, uint32_t a2,
                                     uint32_t a3, uint32_t b0, uint32_t b1) {
    asm volatile(
        "mma.sync.aligned.m16n8k8.row.col.f32.tf32.tf32.f32 "
        "{%0,%1,%2,%3},{%4,%5,%6,%7},{%8,%9},{%0,%1,%2,%3};"
        : "+f"(c[0]), "+f"(c[1]), "+f"(c[2]), "+f"(c[3])
        : "r"(a0), "r"(a1), "r"(a2), "r"(a3), "r"(b0), "r"(b1));
}

// ---------------- tf32 tensor-core GEMM ----------------
// MODE 0: bias, 1: bias+gelu(exact), 2: bias+residual, 3: fused QKV (3 B/bias/C sets)
#define GRP_PAIRS 513
#define BUF_U32   (4 * GRP_PAIRS * 2)        // 4104
#define DBUF_U32  (2 * BUF_U32)              // A+B per stage: 8208
#define GEMM_SMEM (2 * DBUF_U32 * 4)         // bytes: 65664

template <int MODE>
__global__ __launch_bounds__(256) void tgemm(
    const float* __restrict__ A,
    const float* __restrict__ B0, const float* __restrict__ B1, const float* __restrict__ B2,
    const float* __restrict__ bias0, const float* __restrict__ bias1, const float* __restrict__ bias2,
    const float* __restrict__ res, float* __restrict__ C0, float* __restrict__ C1,
    float* __restrict__ C2, int M, int N, int K)
{
    extern __shared__ uint32_t smu[];
    int m0 = blockIdx.y * 128;
    int n0 = blockIdx.x * 128;
    const float* B = B0;
    const float* bias = bias0;
    float* C = C0;
    if (MODE == 3) {
        int ws = n0 >> 10;
        if (ws == 1) { B = B1; bias = bias1; C = C1; }
        else if (ws == 2) { B = B2; bias = bias2; C = C2; }
        n0 &= 1023;
    }

    const int t = threadIdx.x;
    const int quad = t & 7;
    const int rbase = t >> 3;
    const int g8l = quad >> 1;
    const int half = quad & 1;
    const int warp = t >> 5, lane = t & 31;
    const int wm = (warp >> 2) * 64, wn = (warp & 3) * 32;
    const int g = lane >> 2, tig = lane & 3;

    float acc[4][4][4];
#pragma unroll
    for (int i = 0; i < 4; i++)
#pragma unroll
        for (int j = 0; j < 4; j++)
#pragma unroll
            for (int q = 0; q < 4; q++) acc[i][j][q] = 0.f;

    float4 ra[4], rb[4];
    const int NC = K >> 5;

#pragma unroll
    for (int p = 0; p < 4; p++) {
        int gm = m0 + p * 32 + rbase;
        ra[p] = (gm < M) ? *(const float4*)&A[(size_t)gm * K + quad * 4]
                         : make_float4(0.f, 0.f, 0.f, 0.f);
        int gn = n0 + p * 32 + rbase;
        rb[p] = *(const float4*)&B[(size_t)gn * K + quad * 4];
    }
    {
        uint32_t* da = smu + g8l * (GRP_PAIRS * 2) + half;
        uint32_t* db = da + BUF_U32;
#pragma unroll
        for (int p = 0; p < 4; p++) {
            uint32_t* d = da + (p * 32 + rbase) * 8;
            d[0] = f2tf(ra[p].x); d[2] = f2tf(ra[p].y);
            d[4] = f2tf(ra[p].z); d[6] = f2tf(ra[p].w);
            uint32_t* e = db + (p * 32 + rbase) * 8;
            e[0] = f2tf(rb[p].x); e[2] = f2tf(rb[p].y);
            e[4] = f2tf(rb[p].z); e[6] = f2tf(rb[p].w);
        }
    }
    __syncthreads();

    for (int c = 0; c < NC; c++) {
        if (c + 1 < NC) {
            int k0n = (c + 1) << 5;
#pragma unroll
            for (int p = 0; p < 4; p++) {
                int gm = m0 + p * 32 + rbase;
                ra[p] = (gm < M) ? *(const float4*)&A[(size_t)gm * K + k0n + quad * 4]
                                 : make_float4(0.f, 0.f, 0.f, 0.f);
                int gn = n0 + p * 32 + rbase;
                rb[p] = *(const float4*)&B[(size_t)gn * K + k0n + quad * 4];
            }
        }
        const uint32_t* a = smu + (c & 1) * DBUF_U32;
        const uint32_t* bsh = a + BUF_U32;
#pragma unroll
        for (int gg = 0; gg < 4; gg++) {
            uint2 pa[4][2];
            uint2 pb[4];
#pragma unroll
            for (int fm = 0; fm < 4; fm++) {
                int r = wm + fm * 16 + g;
                pa[fm][0] = *(const uint2*)&a[(gg * GRP_PAIRS + r * 4 + tig) * 2];
                pa[fm][1] = *(const uint2*)&a[(gg * GRP_PAIRS + (r + 8) * 4 + tig) * 2];
            }
#pragma unroll
            for (int fn = 0; fn < 4; fn++) {
                int ci = wn + fn * 8 + g;
                pb[fn] = *(const uint2*)&bsh[(gg * GRP_PAIRS + ci * 4 + tig) * 2];
            }
#pragma unroll
            for (int fm = 0; fm < 4; fm++)
#pragma unroll
                for (int fn = 0; fn < 4; fn++)
                    mma8(acc[fm][fn], pa[fm][0].x, pa[fm][1].x, pa[fm][0].y, pa[fm][1].y,
                         pb[fn].x, pb[fn].y);
        }
        if (c + 1 < NC) {
            uint32_t* da = smu + ((c + 1) & 1) * DBUF_U32 + g8l * (GRP_PAIRS * 2) + half;
            uint32_t* db = da + BUF_U32;
#pragma unroll
            for (int p = 0; p < 4; p++) {
                uint32_t* d = da + (p * 32 + rbase) * 8;
                d[0] = f2tf(ra[p].x); d[2] = f2tf(ra[p].y);
                d[4] = f2tf(ra[p].z); d[6] = f2tf(ra[p].w);
                uint32_t* e = db + (p * 32 + rbase) * 8;
                e[0] = f2tf(rb[p].x); e[2] = f2tf(rb[p].y);
                e[4] = f2tf(rb[p].z); e[6] = f2tf(rb[p].w);
            }
        }
        __syncthreads();
    }

#pragma unroll
    for (int fm = 0; fm < 4; fm++) {
        int r0 = m0 + wm + fm * 16 + g;
#pragma unroll
        for (int fn = 0; fn < 4; fn++) {
            int col = n0 + wn + fn * 8 + 2 * tig;
            float b0v = bias[col], b1v = bias[col + 1];
#pragma unroll
            for (int hrow = 0; hrow < 2; hrow++) {
                int r = r0 + hrow * 8;
                if (r >= M) continue;
                float v0 = acc[fm][fn][hrow * 2 + 0] + b0v;
                float v1 = acc[fm][fn][hrow * 2 + 1] + b1v;
                if (MODE == 1) {
                    v0 = 0.5f * v0 * (1.f + erff(v0 * 0.70710678118654752f));
                    v1 = 0.5f * v1 * (1.f + erff(v1 * 0.70710678118654752f));
                }
                if (MODE == 2) {
                    const float* rr = &res[(size_t)r * N + col];
                    v0 += rr[0]; v1 += rr[1];
                }
                *(float2*)&C[(size_t)r * N + col] = make_float2(v0, v1);
            }
        }
    }
}

// ---------------- LayerNorm ----------------
__global__ __launch_bounds__(256) void ln_k(
    const float* __restrict__ x, const float* __restrict__ g,
    const float* __restrict__ b, float* __restrict__ y)
{
    __shared__ float red[8];
    __shared__ float stat[2];
    int row = blockIdx.x, tid = threadIdx.x;
    const float* xr = x + (size_t)row * HIDDEN;
    float v[4];
    float s = 0.f;
#pragma unroll
    for (int i = 0; i < 4; i++) { v[i] = xr[tid + i * 256]; s += v[i]; }
#pragma unroll
    for (int o = 16; o > 0; o >>= 1) s += __shfl_xor_sync(~0u, s, o);
    if ((tid & 31) == 0) red[tid >> 5] = s;
    __syncthreads();
    if (tid < 32) {
        float t = (tid < 8) ? red[tid] : 0.f;
#pragma unroll
        for (int o = 4; o > 0; o >>= 1) t += __shfl_xor_sync(~0u, t, o);
        if (tid == 0) stat[0] = t * (1.f / HIDDEN);
    }
    __syncthreads();
    float mu = stat[0];
    float s2 = 0.f;
#pragma unroll
    for (int i = 0; i < 4; i++) { float d = v[i] - mu; s2 += d * d; }
#pragma unroll
    for (int o = 16; o > 0; o >>= 1) s2 += __shfl_xor_sync(~0u, s2, o);
    if ((tid & 31) == 0) red[tid >> 5] = s2;
    __syncthreads();
    if (tid < 32) {
        float t = (tid < 8) ? red[tid] : 0.f;
#pragma unroll
        for (int o = 4; o > 0; o >>= 1) t += __shfl_xor_sync(~0u, t, o);
        if (tid == 0) stat[1] = rsqrtf(t * (1.f / HIDDEN) + 1e-6f);
    }
    __syncthreads();
    float rs = stat[1];
    float* yr = y + (size_t)row * HIDDEN;
#pragma unroll
    for (int i = 0; i < 4; i++) {
        int c = tid + i * 256;
        yr[c] = (v[i] - mu) * rs * g[c] + b[c];
    }
}

// ---------------- RoPE ----------------
__global__ void rope_k(float* __restrict__ q, float* __restrict__ k) {
    int idx = blockIdx.x * 256 + threadIdx.x;
    const int TOTAL = ROWS * HEADS * 30;
    if (idx >= TOTAL) return;
    int pair = idx % 30;
    int t = idx / 30;
    int h = t & 15;
    int bn = t >> 4;
    int n = bn % NTOK;
    int a = pair / 10, i = pair - a * 10;
    int dpos = n / 196, r = n - dpos * 196;
    int pos = (a == 0) ? dpos : (a == 1) ? (r / 14) : (r % 14);
    int i0 = (2 * i) % 10, i1 = (2 * i + 1) % 10;
    const float LN1E4_O10 = 0.92103403719761840f;
    float f0 = (float)pos * expf(-LN1E4_O10 * (float)i0);
    float f1 = (float)pos * expf(-LN1E4_O10 * (float)i1);
    float s0, c0, s1, c1;
    sincosf(f0, &s0, &c0);
    sincosf(f1, &s1, &c1);
    size_t base = (size_t)bn * HIDDEN + h * HEADD + a * 20 + 2 * i;
    float q0 = q[base], q1 = q[base + 1];
    q[base]     = q0 * c0 - q1 * s0;
    q[base + 1] = q1 * c1 + q0 * s1;
    float k0 = k[base], k1 = k[base + 1];
    k[base]     = k0 * c0 - k1 * s0;
    k[base + 1] = k1 * c1 + k0 * s1;
}

// ---------------- Flash attention via tf32 tensor cores ----------------
// CTA: 64 queries x one (b,h). 4 warps, each owns 16 q rows (m16).
// Loop over 25 key tiles of 64. S via mma (QK^T), online softmax on C frags,
// P through per-warp smem (C-frag -> A-frag relayout), O += P.V via mma.
#define KST 68   // Ks row stride (u32): b-frag reads (4g+tq)%32 distinct
#define VST 72   // Vs row stride: (8tq+g)%32 distinct
#define PST 68   // P row stride: a-frag reads (4g+tq)%32 distinct
#define ATTN_SMEM ((64 * KST + 64 * VST + 64 * PST) * 4)

__global__ __launch_bounds__(128) void attn_mma(
    const float* __restrict__ Q, const float* __restrict__ K,
    const float* __restrict__ V, float* __restrict__ O)
{
    extern __shared__ uint32_t smem[];
    uint32_t* Ks = smem;                 // [64][KST]
    uint32_t* Vs = Ks + 64 * KST;        // [64][VST]
    uint32_t* Ps = Vs + 64 * VST;        // [4][16][PST]

    int b = blockIdx.y >> 4, h = blockIdx.y & 15;
    int q0 = blockIdx.x * 64;
    int tid = threadIdx.x, w = tid >> 5, lane = tid & 31;
    int g = lane >> 2, tq = lane & 3;

    const float* Qb = Q + (size_t)b * NTOK * HIDDEN + h * HEADD;
    const float* Kb = K + (size_t)b * NTOK * HIDDEN + h * HEADD;
    const float* Vb = V + (size_t)b * NTOK * HIDDEN + h * HEADD;

    // Q fragments (A operand), pre-scaled by 1/8
    uint32_t qa[8][4];
    int qrow0 = q0 + w * 16 + g;
    int qrow1 = qrow0 + 8;
    bool qv0 = qrow0 < NTOK, qv1 = qrow1 < NTOK;
    const float* qp0 = Qb + (size_t)qrow0 * HIDDEN;
    const float* qp1 = Qb + (size_t)qrow1 * HIDDEN;
#pragma unroll
    for (int ks = 0; ks < 8; ks++) {
        int d0 = ks * 8 + tq;
        qa[ks][0] = f2tf(qv0 ? qp0[d0] * 0.125f : 0.f);
        qa[ks][1] = f2tf(qv1 ? qp1[d0] * 0.125f : 0.f);
        qa[ks][2] = f2tf(qv0 ? qp0[d0 + 4] * 0.125f : 0.f);
        qa[ks][3] = f2tf(qv1 ? qp1[d0 + 4] * 0.125f : 0.f);
    }

    float oacc[8][4];
#pragma unroll
    for (int i = 0; i < 8; i++)
#pragma unroll
        for (int j = 0; j < 4; j++) oacc[i][j] = 0.f;
    float m0 = -1e30f, m1 = -1e30f, l0 = 0.f, l1 = 0.f;

    uint32_t* pw = Ps + w * 16 * PST;

    for (int kt = 0; kt < 25; kt++) {
        int k0 = kt * 64;
        __syncthreads();
        // stage K,V tiles (64x64) as tf32
#pragma unroll
        for (int i = 0; i < 8; i++) {
            int e = tid + i * 128;          // over 1024 float4 slots
            int r = e >> 4, c4 = (e & 15) * 4;
            int ki = k0 + r;
            float4 kv, vv;
            if (ki < NTOK) {
                kv = *(const float4*)&Kb[(size_t)ki * HIDDEN + c4];
                vv = *(const float4*)&Vb[(size_t)ki * HIDDEN + c4];
            } else {
                kv = make_float4(0.f, 0.f, 0.f, 0.f);
                vv = kv;
            }
            uint32_t* kd = &Ks[r * KST + c4];
            kd[0] = f2tf(kv.x); kd[1] = f2tf(kv.y); kd[2] = f2tf(kv.z); kd[3] = f2tf(kv.w);
            uint32_t* vd = &Vs[r * VST + c4];
            vd[0] = f2tf(vv.x); vd[1] = f2tf(vv.y); vd[2] = f2tf(vv.z); vd[3] = f2tf(vv.w);
        }
        __syncthreads();

        // S = Q.K^T : 8 key-blocks of n8
        float sacc[8][4];
#pragma unroll
        for (int nf = 0; nf < 8; nf++) {
            sacc[nf][0] = 0.f; sacc[nf][1] = 0.f; sacc[nf][2] = 0.f; sacc[nf][3] = 0.f;
            const uint32_t* krow = &Ks[(nf * 8 + g) * KST];
#pragma unroll
            for (int ks = 0; ks < 8; ks++) {
                uint32_t b0 = krow[ks * 8 + tq];
                uint32_t b1 = krow[ks * 8 + tq + 4];
                mma8(sacc[nf], qa[ks][0], qa[ks][1], qa[ks][2], qa[ks][3], b0, b1);
            }
        }

        // mask invalid keys + row max
        float mx0 = -1e30f, mx1 = -1e30f;
#pragma unroll
        for (int nf = 0; nf < 8; nf++) {
            int col0 = k0 + nf * 8 + 2 * tq;
            if (col0 >= NTOK)     { sacc[nf][0] = -1e30f; sacc[nf][2] = -1e30f; }
            if (col0 + 1 >= NTOK) { sacc[nf][1] = -1e30f; sacc[nf][3] = -1e30f; }
            mx0 = fmaxf(mx0, fmaxf(sacc[nf][0], sacc[nf][1]));
            mx1 = fmaxf(mx1, fmaxf(sacc[nf][2], sacc[nf][3]));
        }
        mx0 = fmaxf(mx0, __shfl_xor_sync(~0u, mx0, 1));
        mx0 = fmaxf(mx0, __shfl_xor_sync(~0u, mx0, 2));
        mx1 = fmaxf(mx1, __shfl_xor_sync(~0u, mx1, 1));
        mx1 = fmaxf(mx1, __shfl_xor_sync(~0u, mx1, 2));
        float mn0 = fmaxf(m0, mx0), mn1 = fmaxf(m1, mx1);
        float corr0 = __expf(m0 - mn0), corr1 = __expf(m1 - mn1);
        m0 = mn0; m1 = mn1;

        float ls0 = 0.f, ls1 = 0.f;
#pragma unroll
        for (int nf = 0; nf < 8; nf++) {
            float p0 = __expf(sacc[nf][0] - mn0);
            float p1 = __expf(sacc[nf][1] - mn0);
            float p2 = __expf(sacc[nf][2] - mn1);
            float p3 = __expf(sacc[nf][3] - mn1);
            ls0 += p0 + p1; ls1 += p2 + p3;
            *(uint2*)&pw[g * PST + nf * 8 + 2 * tq]       = make_uint2(f2tf(p0), f2tf(p1));
            *(uint2*)&pw[(g + 8) * PST + nf * 8 + 2 * tq] = make_uint2(f2tf(p2), f2tf(p3));
        }
        ls0 += __shfl_xor_sync(~0u, ls0, 1);
        ls0 += __shfl_xor_sync(~0u, ls0, 2);
        ls1 += __shfl_xor_sync(~0u, ls1, 1);
        ls1 += __shfl_xor_sync(~0u, ls1, 2);
        l0 = l0 * corr0 + ls0;
        l1 = l1 * corr1 + ls1;
#pragma unroll
        for (int nf2 = 0; nf2 < 8; nf2++) {
            oacc[nf2][0] *= corr0; oacc[nf2][1] *= corr0;
            oacc[nf2][2] *= corr1; oacc[nf2][3] *= corr1;
        }
        __syncwarp();

        // O += P.V
#pragma unroll
        for (int ks = 0; ks < 8; ks++) {
            uint32_t a0 = pw[g * PST + ks * 8 + tq];
            uint32_t a1 = pw[(g + 8) * PST + ks * 8 + tq];
            uint32_t a2 = pw[g * PST + ks * 8 + tq + 4];
            uint32_t a3 = pw[(g + 8) * PST + ks * 8 + tq + 4];
            const uint32_t* vr0 = &Vs[(ks * 8 + tq) * VST];
            const uint32_t* vr1 = &Vs[(ks * 8 + tq + 4) * VST];
#pragma unroll
            for (int nf2 = 0; nf2 < 8; nf2++) {
                mma8(oacc[nf2], a0, a1, a2, a3, vr0[nf2 * 8 + g], vr1[nf2 * 8 + g]);
            }
        }
        __syncwarp();
    }

    float inv0 = 1.f / l0, inv1 = 1.f / l1;
    float* Ob = O + (size_t)b * NTOK * HIDDEN + h * HEADD;
#pragma unroll
    for (int nf2 = 0; nf2 < 8; nf2++) {
        int d0 = nf2 * 8 + 2 * tq;
        if (qv0)
            *(float2*)&Ob[(size_t)qrow0 * HIDDEN + d0] =
                make_float2(oacc[nf2][0] * inv0, oacc[nf2][1] * inv0);
        if (qv1)
            *(float2*)&Ob[(size_t)qrow1 * HIDDEN + d0] =
                make_float2(oacc[nf2][2] * inv1, oacc[nf2][3] * inv1);
    }
}

// ---------------- host orchestration ----------------
extern "C" void kernel_launch(void* const* d_in, const int* in_sizes, int n_in,
                              void* d_out, int out_size) {
    (void)in_sizes; (void)n_in; (void)out_size;
    const float* px      = (const float*)d_in[0];
    const float* patch_w = (const float*)d_in[1];
    const float* patch_b = (const float*)d_in[2];
    const float* ln1g = (const float*)d_in[3];
    const float* ln1b = (const float*)d_in[4];
    const float* qw = (const float*)d_in[5];
    const float* qb = (const float*)d_in[6];
    const float* kw = (const float*)d_in[7];
    const float* kb = (const float*)d_in[8];
    const float* vw = (const float*)d_in[9];
    const float* vb = (const float*)d_in[10];
    const float* pw = (const float*)d_in[11];
    const float* pb = (const float*)d_in[12];
    const float* ln2g = (const float*)d_in[13];
    const float* ln2b = (const float*)d_in[14];
    const float* fc1w = (const float*)d_in[15];
    const float* fc1b = (const float*)d_in[16];
    const float* fc2w = (const float*)d_in[17];
    const float* fc2b = (const float*)d_in[18];
    const float* lnfg = (const float*)d_in[19];
    const float* lnfb = (const float*)d_in[20];
    float* out = (float*)d_out;

    void *ph, *pxn, *pq, *pk, *pv, *pao, *pmlp, *pcol;
    cudaGetSymbolAddress(&ph,  g_h);
    cudaGetSymbolAddress(&pxn, g_xn);
    cudaGetSymbolAddress(&pq,  g_q);
    cudaGetSymbolAddress(&pk,  g_k);
    cudaGetSymbolAddress(&pv,  g_v);
    cudaGetSymbolAddress(&pao, g_ao);
    cudaGetSymbolAddress(&pmlp, g_mlp);
    cudaGetSymbolAddress(&pcol, g_col);
    float* h   = (float*)ph;
    float* xn  = (float*)pxn;
    float* q   = (float*)pq;
    float* k   = (float*)pk;
    float* v   = (float*)pv;
    float* ao  = (float*)pao;
    float* mlp = (float*)pmlp;
    float* col = (float*)pcol;

    cudaFuncSetAttribute(attn_mma, cudaFuncAttributeMaxDynamicSharedMemorySize, ATTN_SMEM);
    cudaFuncSetAttribute(tgemm<0>, cudaFuncAttributeMaxDynamicSharedMemorySize, GEMM_SMEM);
    cudaFuncSetAttribute(tgemm<1>, cudaFuncAttributeMaxDynamicSharedMemorySize, GEMM_SMEM);
    cudaFuncSetAttribute(tgemm<2>, cudaFuncAttributeMaxDynamicSharedMemorySize, GEMM_SMEM);
    cudaFuncSetAttribute(tgemm<3>, cudaFuncAttributeMaxDynamicSharedMemorySize, GEMM_SMEM);

    // patch embed
    im2col_k<<<(ROWS * PATCH_K + 255) / 256, 256>>>(px, col);
    tgemm<0><<<dim3(HIDDEN / 128, 25), 256, GEMM_SMEM>>>(
        col, patch_w, patch_w, patch_w, patch_b, patch_b, patch_b,
        nullptr, h, h, h, ROWS, HIDDEN, PATCH_K);

    for (int l = 0; l < LAYERS; l++) {
        size_t wo = (size_t)l * HIDDEN * HIDDEN;
        size_t bo = (size_t)l * HIDDEN;
        // attention block
        ln_k<<<ROWS, 256>>>(h, ln1g + bo, ln1b + bo, xn);
        tgemm<3><<<dim3(24, 25), 256, GEMM_SMEM>>>(
            xn, qw + wo, kw + wo, vw + wo, qb + bo, kb + bo, vb + bo,
            nullptr, q, k, v, ROWS, HIDDEN, HIDDEN);
        rope_k<<<(ROWS * HEADS * 30 + 255) / 256, 256>>>(q, k);
        attn_mma<<<dim3(25, BATCH * HEADS), 128, ATTN_SMEM>>>(q, k, v, ao);
        tgemm<2><<<dim3(8, 25), 256, GEMM_SMEM>>>(
            ao, pw + wo, pw + wo, pw + wo, pb + bo, pb + bo, pb + bo,
            h, h, h, h, ROWS, HIDDEN, HIDDEN);
        // MLP block
        ln_k<<<ROWS, 256>>>(h, ln2g + bo, ln2b + bo, xn);
        tgemm<1><<<dim3(MLPD / 128, 25), 256, GEMM_SMEM>>>(
            xn, fc1w + (size_t)l * MLPD * HIDDEN, fc1w, fc1w,
            fc1b + (size_t)l * MLPD, fc1b, fc1b,
            nullptr, mlp, mlp, mlp, ROWS, MLPD, HIDDEN);
        tgemm<2><<<dim3(8, 25), 256, GEMM_SMEM>>>(
            mlp, fc2w + (size_t)l * HIDDEN * MLPD, fc2w, fc2w,
            fc2b + bo, fc2b, fc2b,
            h, h, h, h, ROWS, HIDDEN, MLPD);
    }

    ln_k<<<ROWS, 256>>>(h, lnfg, lnfb, out);
}

// round 5
// speedup vs baseline: 3.5160x; 1.1369x over previous
#include <cuda_runtime.h>
#include <cuda_bf16.h>
#include <math.h>
#include <stdint.h>

#define HIDDEN 1024
#define HEADS 16
#define HEADD 64
#define LAYERS 4
#define MLPD 4096
#define NTOK 1568
#define BATCH 2
#define ROWS (BATCH * NTOK)          // 3136
#define PATCH_K 1536                 // 3*2*16*16
#define MEG (1 << 20)

// ---------------- scratch (device globals; no allocation allowed) ----------------
__device__ float g_h  [ROWS * HIDDEN];
__device__ float g_xn [ROWS * HIDDEN];
__device__ float g_q  [ROWS * HIDDEN];
__device__ float g_k  [ROWS * HIDDEN];
__device__ float g_v  [ROWS * HIDDEN];
__device__ float g_ao [ROWS * HIDDEN];
__device__ float g_mlp[ROWS * MLPD];
__device__ float g_col[ROWS * PATCH_K];
__device__ float g_wr [12 * MEG];    // per-layer rounded weights (or patch embed)

__device__ __forceinline__ uint32_t f2tf(float x) {
    uint32_t u;
    asm("cvt.rna.tf32.f32 %0, %1;" : "=r"(u) : "f"(x));
    return u;
}
__device__ __forceinline__ float f2tff(float x) { return __uint_as_float(f2tf(x)); }

// ---------------- weight rounding ----------------
__global__ void round4_k(const float* __restrict__ in, float* __restrict__ out, int n4) {
    int i = blockIdx.x * 256 + threadIdx.x;
    if (i >= n4) return;
    float4 v = ((const float4*)in)[i];
    ((uint4*)out)[i] = make_uint4(f2tf(v.x), f2tf(v.y), f2tf(v.z), f2tf(v.w));
}

// rounds one layer's weights (qw,kw,vw,pw:1M floats each; fc1,fc2:4M each) into g_wr
__global__ void round_layer_k(const float* __restrict__ qw, const float* __restrict__ kw,
                              const float* __restrict__ vw, const float* __restrict__ pw,
                              const float* __restrict__ f1, const float* __restrict__ f2,
                              float* __restrict__ out) {
    int i = blockIdx.x * 256 + threadIdx.x;      // float4 index, total 3*2^20
    if (i >= 3 * MEG) return;
    int u = i >> 18;
    const float* src;
    int base;
    if (u < 4) {
        src = (u == 0) ? qw : (u == 1) ? kw : (u == 2) ? vw : pw;
        base = i & 262143;
    } else if (u < 8) { src = f1; base = i - 4 * 262144; }
    else             { src = f2; base = i - 8 * 262144; }
    float4 v = ((const float4*)src)[base];
    ((uint4*)out)[i] = make_uint4(f2tf(v.x), f2tf(v.y), f2tf(v.z), f2tf(v.w));
}

// ---------------- im2col (stores tf32-rounded) ----------------
__global__ void im2col_k(const float* __restrict__ px, float* __restrict__ col) {
    int idx = blockIdx.x * 256 + threadIdx.x;
    if (idx >= ROWS * PATCH_K) return;
    int m = idx / PATCH_K;
    int j = idx - m * PATCH_K;
    int c  = j >> 9;
    int r  = j & 511;
    int t  = r >> 8;
    int ph = (r >> 4) & 15;
    int pw = r & 15;
    int b = m / NTOK;
    int n = m - b * NTOK;
    int d  = n / 196;
    int rr = n - d * 196;
    int hy = rr / 14;
    int wx = rr - hy * 14;
    size_t src = ((size_t)((b * 16 + d * 2 + t) * 3 + c)) * (224 * 224)
               + (size_t)(hy * 16 + ph) * 224 + (wx * 16 + pw);
    col[idx] = f2tff(px[src]);
}

// ---------------- tf32 tensor-core GEMM (inputs pre-rounded to tf32) ----------------
// MODE 0: bias, 1: bias+gelu(out rounded), 2: bias+residual, 3: fused QKV
__device__ __forceinline__ void mma8(float* c, uint32_t a0, uint32_t a1, uint32_t a2,
                                     uint32_t a3, uint32_t b0, uint32_t b1) {
    asm volatile(
        "mma.sync.aligned.m16n8k8.row.col.f32.tf32.tf32.f32 "
        "{%0,%1,%2,%3},{%4,%5,%6,%7},{%8,%9},{%0,%1,%2,%3};"
        : "+f"(c[0]), "+f"(c[1]), "+f"(c[2]), "+f"(c[3])
        : "r"(a0), "r"(a1), "r"(a2), "r"(a3), "r"(b0), "r"(b1));
}

#define GRP_PAIRS 513
#define BUF_U32   (4 * GRP_PAIRS * 2)        // 4104
#define DBUF_U32  (2 * BUF_U32)              // A+B per stage: 8208
#define GEMM_SMEM (2 * DBUF_U32 * 4)         // bytes: 65664

template <int MODE>
__global__ __launch_bounds__(256, 2) void tgemm(
    const float* __restrict__ A,
    const float* __restrict__ B0, const float* __restrict__ B1, const float* __restrict__ B2,
    const float* __restrict__ bias0, const float* __restrict__ bias1, const float* __restrict__ bias2,
    const float* __restrict__ res, float* __restrict__ C0, float* __restrict__ C1,
    float* __restrict__ C2, int M, int N, int K)
{
    extern __shared__ uint32_t smu[];
    int m0 = blockIdx.y * 128;
    int n0 = blockIdx.x * 128;
    const float* B = B0;
    const float* bias = bias0;
    float* C = C0;
    if (MODE == 3) {
        int ws = n0 >> 10;
        if (ws == 1) { B = B1; bias = bias1; C = C1; }
        else if (ws == 2) { B = B2; bias = bias2; C = C2; }
        n0 &= 1023;
    }

    const int t = threadIdx.x;
    const int quad = t & 7;
    const int rbase = t >> 3;
    const int g8l = quad >> 1;
    const int half = quad & 1;
    const int warp = t >> 5, lane = t & 31;
    const int wm = (warp >> 2) * 64, wn = (warp & 3) * 32;
    const int g = lane >> 2, tig = lane & 3;

    float acc[4][4][4];
#pragma unroll
    for (int i = 0; i < 4; i++)
#pragma unroll
        for (int j = 0; j < 4; j++)
#pragma unroll
            for (int q = 0; q < 4; q++) acc[i][j][q] = 0.f;

    const int NC = K >> 5;

    // prologue: stage chunk 0 (raw bit copy; inputs already tf32-rounded)
    {
        uint32_t* da = smu + g8l * (GRP_PAIRS * 2) + half;
        uint32_t* db = da + BUF_U32;
#pragma unroll
        for (int p = 0; p < 4; p++) {
            int gm = m0 + p * 32 + rbase;
            uint4 va = (gm < M) ? *(const uint4*)&A[(size_t)gm * K + quad * 4]
                                : make_uint4(0u, 0u, 0u, 0u);
            uint32_t* d = da + (p * 32 + rbase) * 8;
            d[0] = va.x; d[2] = va.y; d[4] = va.z; d[6] = va.w;
            int gn = n0 + p * 32 + rbase;
            uint4 vb = *(const uint4*)&B[(size_t)gn * K + quad * 4];
            uint32_t* e = db + (p * 32 + rbase) * 8;
            e[0] = vb.x; e[2] = vb.y; e[4] = vb.z; e[6] = vb.w;
        }
    }
    __syncthreads();

    for (int c = 0; c < NC; c++) {
        const uint32_t* a = smu + (c & 1) * DBUF_U32;
        const uint32_t* bsh = a + BUF_U32;
        bool more = (c + 1 < NC);
        int k0n = (c + 1) << 5;
        uint32_t* da = smu + ((c + 1) & 1) * DBUF_U32 + g8l * (GRP_PAIRS * 2) + half;
        uint32_t* db = da + BUF_U32;

        auto comp = [&](int gg) {
            uint2 pa[4][2];
            uint2 pb[4];
#pragma unroll
            for (int fm = 0; fm < 4; fm++) {
                int r = wm + fm * 16 + g;
                pa[fm][0] = *(const uint2*)&a[(gg * GRP_PAIRS + r * 4 + tig) * 2];
                pa[fm][1] = *(const uint2*)&a[(gg * GRP_PAIRS + (r + 8) * 4 + tig) * 2];
            }
#pragma unroll
            for (int fn = 0; fn < 4; fn++) {
                int ci = wn + fn * 8 + g;
                pb[fn] = *(const uint2*)&bsh[(gg * GRP_PAIRS + ci * 4 + tig) * 2];
            }
#pragma unroll
            for (int fm = 0; fm < 4; fm++)
#pragma unroll
                for (int fn = 0; fn < 4; fn++)
                    mma8(acc[fm][fn], pa[fm][0].x, pa[fm][1].x, pa[fm][0].y, pa[fm][1].y,
                         pb[fn].x, pb[fn].y);
        };
        auto lda = [&](int p) -> uint4 {
            int gm = m0 + p * 32 + rbase;
            return (gm < M) ? *(const uint4*)&A[(size_t)gm * K + k0n + quad * 4]
                            : make_uint4(0u, 0u, 0u, 0u);
        };
        auto ldb = [&](int p) -> uint4 {
            int gn = n0 + p * 32 + rbase;
            return *(const uint4*)&B[(size_t)gn * K + k0n + quad * 4];
        };
        auto sta = [&](uint4 v, int p) {
            uint32_t* d = da + (p * 32 + rbase) * 8;
            d[0] = v.x; d[2] = v.y; d[4] = v.z; d[6] = v.w;
        };
        auto stb = [&](uint4 v, int p) {
            uint32_t* d = db + (p * 32 + rbase) * 8;
            d[0] = v.x; d[2] = v.y; d[4] = v.z; d[6] = v.w;
        };

        uint4 ra0, ra1, rb0, rb1;
        comp(0);
        if (more) { ra0 = lda(0); ra1 = lda(1); rb0 = ldb(0); rb1 = ldb(1); }
        comp(1);
        if (more) {
            sta(ra0, 0); sta(ra1, 1); stb(rb0, 0); stb(rb1, 1);
            ra0 = lda(2); ra1 = lda(3); rb0 = ldb(2); rb1 = ldb(3);
        }
        comp(2);
        if (more) { sta(ra0, 2); sta(ra1, 3); stb(rb0, 2); stb(rb1, 3); }
        comp(3);
        __syncthreads();
    }

    // epilogue
#pragma unroll
    for (int fm = 0; fm < 4; fm++) {
        int r0 = m0 + wm + fm * 16 + g;
#pragma unroll
        for (int fn = 0; fn < 4; fn++) {
            int col = n0 + wn + fn * 8 + 2 * tig;
            float b0v = bias[col], b1v = bias[col + 1];
#pragma unroll
            for (int hrow = 0; hrow < 2; hrow++) {
                int r = r0 + hrow * 8;
                if (r >= M) continue;
                float v0 = acc[fm][fn][hrow * 2 + 0] + b0v;
                float v1 = acc[fm][fn][hrow * 2 + 1] + b1v;
                if (MODE == 1) {
                    v0 = f2tff(0.5f * v0 * (1.f + erff(v0 * 0.70710678118654752f)));
                    v1 = f2tff(0.5f * v1 * (1.f + erff(v1 * 0.70710678118654752f)));
                }
                if (MODE == 2) {
                    const float* rr = &res[(size_t)r * N + col];
                    v0 += rr[0]; v1 += rr[1];
                }
                *(float2*)&C[(size_t)r * N + col] = make_float2(v0, v1);
            }
        }
    }
}

// ---------------- LayerNorm (output tf32-rounded; feeds GEMMs only) ----------------
__global__ __launch_bounds__(256) void ln_k(
    const float* __restrict__ x, const float* __restrict__ g,
    const float* __restrict__ b, float* __restrict__ y, int do_round)
{
    __shared__ float red[8];
    __shared__ float stat[2];
    int row = blockIdx.x, tid = threadIdx.x;
    const float* xr = x + (size_t)row * HIDDEN;
    float v[4];
    float s = 0.f;
#pragma unroll
    for (int i = 0; i < 4; i++) { v[i] = xr[tid + i * 256]; s += v[i]; }
#pragma unroll
    for (int o = 16; o > 0; o >>= 1) s += __shfl_xor_sync(~0u, s, o);
    if ((tid & 31) == 0) red[tid >> 5] = s;
    __syncthreads();
    if (tid < 32) {
        float t = (tid < 8) ? red[tid] : 0.f;
#pragma unroll
        for (int o = 4; o > 0; o >>= 1) t += __shfl_xor_sync(~0u, t, o);
        if (tid == 0) stat[0] = t * (1.f / HIDDEN);
    }
    __syncthreads();
    float mu = stat[0];
    float s2 = 0.f;
#pragma unroll
    for (int i = 0; i < 4; i++) { float d = v[i] - mu; s2 += d * d; }
#pragma unroll
    for (int o = 16; o > 0; o >>= 1) s2 += __shfl_xor_sync(~0u, s2, o);
    if ((tid & 31) == 0) red[tid >> 5] = s2;
    __syncthreads();
    if (tid < 32) {
        float t = (tid < 8) ? red[tid] : 0.f;
#pragma unroll
        for (int o = 4; o > 0; o >>= 1) t += __shfl_xor_sync(~0u, t, o);
        if (tid == 0) stat[1] = rsqrtf(t * (1.f / HIDDEN) + 1e-6f);
    }
    __syncthreads();
    float rs = stat[1];
    float* yr = y + (size_t)row * HIDDEN;
#pragma unroll
    for (int i = 0; i < 4; i++) {
        int c = tid + i * 256;
        float o = (v[i] - mu) * rs * g[c] + b[c];
        yr[c] = do_round ? f2tff(o) : o;
    }
}

// ---------------- RoPE ----------------
__global__ void rope_k(float* __restrict__ q, float* __restrict__ k) {
    int idx = blockIdx.x * 256 + threadIdx.x;
    const int TOTAL = ROWS * HEADS * 30;
    if (idx >= TOTAL) return;
    int pair = idx % 30;
    int t = idx / 30;
    int h = t & 15;
    int bn = t >> 4;
    int n = bn % NTOK;
    int a = pair / 10, i = pair - a * 10;
    int dpos = n / 196, r = n - dpos * 196;
    int pos = (a == 0) ? dpos : (a == 1) ? (r / 14) : (r % 14);
    int i0 = (2 * i) % 10, i1 = (2 * i + 1) % 10;
    const float LN1E4_O10 = 0.92103403719761840f;
    float f0 = (float)pos * expf(-LN1E4_O10 * (float)i0);
    float f1 = (float)pos * expf(-LN1E4_O10 * (float)i1);
    float s0, c0, s1, c1;
    sincosf(f0, &s0, &c0);
    sincosf(f1, &s1, &c1);
    size_t base = (size_t)bn * HIDDEN + h * HEADD + a * 20 + 2 * i;
    float q0 = q[base], q1 = q[base + 1];
    q[base]     = q0 * c0 - q1 * s0;
    q[base + 1] = q1 * c1 + q0 * s1;
    float k0 = k[base], k1 = k[base + 1];
    k[base]     = k0 * c0 - k1 * s0;
    k[base + 1] = k1 * c1 + k0 * s1;
}

// ---------------- Flash attention via mma.sync tf32 ----------------
#define KST 68
#define VST 72
#define PST 68
#define ATTN_SMEM ((64 * KST + 64 * VST + 64 * PST) * 4)

__global__ __launch_bounds__(128) void attn_mma(
    const float* __restrict__ Q, const float* __restrict__ K,
    const float* __restrict__ V, float* __restrict__ O)
{
    extern __shared__ uint32_t smem[];
    uint32_t* Ks = smem;
    uint32_t* Vs = Ks + 64 * KST;
    uint32_t* Ps = Vs + 64 * VST;

    int b = blockIdx.y >> 4, h = blockIdx.y & 15;
    int q0 = blockIdx.x * 64;
    int tid = threadIdx.x, w = tid >> 5, lane = tid & 31;
    int g = lane >> 2, tq = lane & 3;

    const float* Qb = Q + (size_t)b * NTOK * HIDDEN + h * HEADD;
    const float* Kb = K + (size_t)b * NTOK * HIDDEN + h * HEADD;
    const float* Vb = V + (size_t)b * NTOK * HIDDEN + h * HEADD;

    uint32_t qa[8][4];
    int qrow0 = q0 + w * 16 + g;
    int qrow1 = qrow0 + 8;
    bool qv0 = qrow0 < NTOK, qv1 = qrow1 < NTOK;
    const float* qp0 = Qb + (size_t)qrow0 * HIDDEN;
    const float* qp1 = Qb + (size_t)qrow1 * HIDDEN;
#pragma unroll
    for (int ks = 0; ks < 8; ks++) {
        int d0 = ks * 8 + tq;
        qa[ks][0] = f2tf(qv0 ? qp0[d0] * 0.125f : 0.f);
        qa[ks][1] = f2tf(qv1 ? qp1[d0] * 0.125f : 0.f);
        qa[ks][2] = f2tf(qv0 ? qp0[d0 + 4] * 0.125f : 0.f);
        qa[ks][3] = f2tf(qv1 ? qp1[d0 + 4] * 0.125f : 0.f);
    }

    float oacc[8][4];
#pragma unroll
    for (int i = 0; i < 8; i++)
#pragma unroll
        for (int j = 0; j < 4; j++) oacc[i][j] = 0.f;
    float m0 = -1e30f, m1 = -1e30f, l0 = 0.f, l1 = 0.f;

    uint32_t* pw = Ps + w * 16 * PST;

    for (int kt = 0; kt < 25; kt++) {
        int k0 = kt * 64;
        __syncthreads();
#pragma unroll
        for (int i = 0; i < 8; i++) {
            int e = tid + i * 128;
            int r = e >> 4, c4 = (e & 15) * 4;
            int ki = k0 + r;
            float4 kv, vv;
            if (ki < NTOK) {
                kv = *(const float4*)&Kb[(size_t)ki * HIDDEN + c4];
                vv = *(const float4*)&Vb[(size_t)ki * HIDDEN + c4];
            } else {
                kv = make_float4(0.f, 0.f, 0.f, 0.f);
                vv = kv;
            }
            uint32_t* kd = &Ks[r * KST + c4];
            kd[0] = f2tf(kv.x); kd[1] = f2tf(kv.y); kd[2] = f2tf(kv.z); kd[3] = f2tf(kv.w);
            uint32_t* vd = &Vs[r * VST + c4];
            vd[0] = f2tf(vv.x); vd[1] = f2tf(vv.y); vd[2] = f2tf(vv.z); vd[3] = f2tf(vv.w);
        }
        __syncthreads();

        float sacc[8][4];
#pragma unroll
        for (int nf = 0; nf < 8; nf++) {
            sacc[nf][0] = 0.f; sacc[nf][1] = 0.f; sacc[nf][2] = 0.f; sacc[nf][3] = 0.f;
            const uint32_t* krow = &Ks[(nf * 8 + g) * KST];
#pragma unroll
            for (int ks = 0; ks < 8; ks++) {
                uint32_t b0 = krow[ks * 8 + tq];
                uint32_t b1 = krow[ks * 8 + tq + 4];
                mma8(sacc[nf], qa[ks][0], qa[ks][1], qa[ks][2], qa[ks][3], b0, b1);
            }
        }

        float mx0 = -1e30f, mx1 = -1e30f;
#pragma unroll
        for (int nf = 0; nf < 8; nf++) {
            int col0 = k0 + nf * 8 + 2 * tq;
            if (col0 >= NTOK)     { sacc[nf][0] = -1e30f; sacc[nf][2] = -1e30f; }
            if (col0 + 1 >= NTOK) { sacc[nf][1] = -1e30f; sacc[nf][3] = -1e30f; }
            mx0 = fmaxf(mx0, fmaxf(sacc[nf][0], sacc[nf][1]));
            mx1 = fmaxf(mx1, fmaxf(sacc[nf][2], sacc[nf][3]));
        }
        mx0 = fmaxf(mx0, __shfl_xor_sync(~0u, mx0, 1));
        mx0 = fmaxf(mx0, __shfl_xor_sync(~0u, mx0, 2));
        mx1 = fmaxf(mx1, __shfl_xor_sync(~0u, mx1, 1));
        mx1 = fmaxf(mx1, __shfl_xor_sync(~0u, mx1, 2));
        float mn0 = fmaxf(m0, mx0), mn1 = fmaxf(m1, mx1);
        float corr0 = __expf(m0 - mn0), corr1 = __expf(m1 - mn1);
        m0 = mn0; m1 = mn1;

        float ls0 = 0.f, ls1 = 0.f;
#pragma unroll
        for (int nf = 0; nf < 8; nf++) {
            float p0 = __expf(sacc[nf][0] - mn0);
            float p1 = __expf(sacc[nf][1] - mn0);
            float p2 = __expf(sacc[nf][2] - mn1);
            float p3 = __expf(sacc[nf][3] - mn1);
            ls0 += p0 + p1; ls1 += p2 + p3;
            *(uint2*)&pw[g * PST + nf * 8 + 2 * tq]       = make_uint2(f2tf(p0), f2tf(p1));
            *(uint2*)&pw[(g + 8) * PST + nf * 8 + 2 * tq] = make_uint2(f2tf(p2), f2tf(p3));
        }
        ls0 += __shfl_xor_sync(~0u, ls0, 1);
        ls0 += __shfl_xor_sync(~0u, ls0, 2);
        ls1 += __shfl_xor_sync(~0u, ls1, 1);
        ls1 += __shfl_xor_sync(~0u, ls1, 2);
        l0 = l0 * corr0 + ls0;
        l1 = l1 * corr1 + ls1;
#pragma unroll
        for (int nf2 = 0; nf2 < 8; nf2++) {
            oacc[nf2][0] *= corr0; oacc[nf2][1] *= corr0;
            oacc[nf2][2] *= corr1; oacc[nf2][3] *= corr1;
        }
        __syncwarp();

#pragma unroll
        for (int ks = 0; ks < 8; ks++) {
            uint32_t a0 = pw[g * PST + ks * 8 + tq];
            uint32_t a1 = pw[(g + 8) * PST + ks * 8 + tq];
            uint32_t a2 = pw[g * PST + ks * 8 + tq + 4];
            uint32_t a3 = pw[(g + 8) * PST + ks * 8 + tq + 4];
            const uint32_t* vr0 = &Vs[(ks * 8 + tq) * VST];
            const uint32_t* vr1 = &Vs[(ks * 8 + tq + 4) * VST];
#pragma unroll
            for (int nf2 = 0; nf2 < 8; nf2++) {
                mma8(oacc[nf2], a0, a1, a2, a3, vr0[nf2 * 8 + g], vr1[nf2 * 8 + g]);
            }
        }
        __syncwarp();
    }

    float inv0 = 1.f / l0, inv1 = 1.f / l1;
    float* Ob = O + (size_t)b * NTOK * HIDDEN + h * HEADD;
#pragma unroll
    for (int nf2 = 0; nf2 < 8; nf2++) {
        int d0 = nf2 * 8 + 2 * tq;
        if (qv0)
            *(float2*)&Ob[(size_t)qrow0 * HIDDEN + d0] =
                make_float2(f2tff(oacc[nf2][0] * inv0), f2tff(oacc[nf2][1] * inv0));
        if (qv1)
            *(float2*)&Ob[(size_t)qrow1 * HIDDEN + d0] =
                make_float2(f2tff(oacc[nf2][2] * inv1), f2tff(oacc[nf2][3] * inv1));
    }
}

// ---------------- host orchestration ----------------
extern "C" void kernel_launch(void* const* d_in, const int* in_sizes, int n_in,
                              void* d_out, int out_size) {
    (void)in_sizes; (void)n_in; (void)out_size;
    const float* px      = (const float*)d_in[0];
    const float* patch_w = (const float*)d_in[1];
    const float* patch_b = (const float*)d_in[2];
    const float* ln1g = (const float*)d_in[3];
    const float* ln1b = (const float*)d_in[4];
    const float* qw = (const float*)d_in[5];
    const float* qb = (const float*)d_in[6];
    const float* kw = (const float*)d_in[7];
    const float* kb = (const float*)d_in[8];
    const float* vw = (const float*)d_in[9];
    const float* vb = (const float*)d_in[10];
    const float* pw = (const float*)d_in[11];
    const float* pb = (const float*)d_in[12];
    const float* ln2g = (const float*)d_in[13];
    const float* ln2b = (const float*)d_in[14];
    const float* fc1w = (const float*)d_in[15];
    const float* fc1b = (const float*)d_in[16];
    const float* fc2w = (const float*)d_in[17];
    const float* fc2b = (const float*)d_in[18];
    const float* lnfg = (const float*)d_in[19];
    const float* lnfb = (const float*)d_in[20];
    float* out = (float*)d_out;

    void *ph, *pxn, *pq, *pk, *pv, *pao, *pmlp, *pcol, *pwr;
    cudaGetSymbolAddress(&ph,  g_h);
    cudaGetSymbolAddress(&pxn, g_xn);
    cudaGetSymbolAddress(&pq,  g_q);
    cudaGetSymbolAddress(&pk,  g_k);
    cudaGetSymbolAddress(&pv,  g_v);
    cudaGetSymbolAddress(&pao, g_ao);
    cudaGetSymbolAddress(&pmlp, g_mlp);
    cudaGetSymbolAddress(&pcol, g_col);
    cudaGetSymbolAddress(&pwr, g_wr);
    float* h   = (float*)ph;
    float* xn  = (float*)pxn;
    float* q   = (float*)pq;
    float* k   = (float*)pk;
    float* v   = (float*)pv;
    float* ao  = (float*)pao;
    float* mlp = (float*)pmlp;
    float* col = (float*)pcol;
    float* wr  = (float*)pwr;

    cudaFuncSetAttribute(attn_mma, cudaFuncAttributeMaxDynamicSharedMemorySize, ATTN_SMEM);
    cudaFuncSetAttribute(tgemm<0>, cudaFuncAttributeMaxDynamicSharedMemorySize, GEMM_SMEM);
    cudaFuncSetAttribute(tgemm<1>, cudaFuncAttributeMaxDynamicSharedMemorySize, GEMM_SMEM);
    cudaFuncSetAttribute(tgemm<2>, cudaFuncAttributeMaxDynamicSharedMemorySize, GEMM_SMEM);
    cudaFuncSetAttribute(tgemm<3>, cudaFuncAttributeMaxDynamicSharedMemorySize, GEMM_SMEM);

    // patch embed (col and patch weights pre-rounded to tf32)
    im2col_k<<<(ROWS * PATCH_K + 255) / 256, 256>>>(px, col);
    round4_k<<<(HIDDEN * PATCH_K / 4 + 255) / 256, 256>>>(patch_w, wr, HIDDEN * PATCH_K / 4);
    tgemm<0><<<dim3(HIDDEN / 128, 25), 256, GEMM_SMEM>>>(
        col, wr, wr, wr, patch_b, patch_b, patch_b,
        nullptr, h, h, h, ROWS, HIDDEN, PATCH_K);

    for (int l = 0; l < LAYERS; l++) {
        size_t wo = (size_t)l * HIDDEN * HIDDEN;
        size_t bo = (size_t)l * HIDDEN;
        round_layer_k<<<(3 * MEG + 255) / 256, 256>>>(
            qw + wo, kw + wo, vw + wo, pw + wo,
            fc1w + (size_t)l * MLPD * HIDDEN, fc2w + (size_t)l * HIDDEN * MLPD, wr);
        // attention block
        ln_k<<<ROWS, 256>>>(h, ln1g + bo, ln1b + bo, xn, 1);
        tgemm<3><<<dim3(24, 25), 256, GEMM_SMEM>>>(
            xn, wr, wr + MEG, wr + 2 * MEG, qb + bo, kb + bo, vb + bo,
            nullptr, q, k, v, ROWS, HIDDEN, HIDDEN);
        rope_k<<<(ROWS * HEADS * 30 + 255) / 256, 256>>>(q, k);
        attn_mma<<<dim3(25, BATCH * HEADS), 128, ATTN_SMEM>>>(q, k, v, ao);
        tgemm<2><<<dim3(8, 25), 256, GEMM_SMEM>>>(
            ao, wr + 3 * MEG, wr, wr, pb + bo, pb + bo, pb + bo,
            h, h, h, h, ROWS, HIDDEN, HIDDEN);
        // MLP block
        ln_k<<<ROWS, 256>>>(h, ln2g + bo, ln2b + bo, xn, 1);
        tgemm<1><<<dim3(MLPD / 128, 25), 256, GEMM_SMEM>>>(
            xn, wr + 4 * MEG, wr, wr, fc1b + (size_t)l * MLPD, fc1b, fc1b,
            nullptr, mlp, mlp, mlp, ROWS, MLPD, HIDDEN);
        tgemm<2><<<dim3(8, 25), 256, GEMM_SMEM>>>(
            mlp, wr + 8 * MEG, wr, wr, fc2b + bo, fc2b, fc2b,
            h, h, h, h, ROWS, HIDDEN, MLPD);
    }

    ln_k<<<ROWS, 256>>>(h, lnfg, lnfb, out, 0);
}

// round 7
// speedup vs baseline: 5.5302x; 1.5729x over previous
#include <cuda_runtime.h>
#include <cuda_fp16.h>
#include <math.h>
#include <stdint.h>

#define HIDDEN 1024
#define HEADS 16
#define HEADD 64
#define LAYERS 4
#define MLPD 4096
#define NTOK 1568
#define BATCH 2
#define ROWS (BATCH * NTOK)          // 3136
#define PATCH_K 1536                 // 3*2*16*16
#define MEG (1 << 20)

// ---------------- scratch (device globals; no allocation allowed) ----------------
__device__ float  g_h  [ROWS * HIDDEN];
__device__ float  g_q  [ROWS * HIDDEN];
__device__ float  g_k  [ROWS * HIDDEN];
__device__ float  g_v  [ROWS * HIDDEN];
__device__ __half g_xnh [ROWS * HIDDEN];
__device__ __half g_aoh [ROWS * HIDDEN];
__device__ __half g_mlph[ROWS * MLPD];
__device__ __half g_colh[ROWS * PATCH_K];
__device__ __half g_wrh [12 * MEG];   // per-layer fp16 weights (or patch embed)

__device__ __forceinline__ uint32_t f2tf(float x) {
    uint32_t u;
    asm("cvt.rna.tf32.f32 %0, %1;" : "=r"(u) : "f"(x));
    return u;
}
__device__ __forceinline__ uint32_t pack2(float a, float b) {
    __half2 h = __floats2half2_rn(a, b);
    return *(uint32_t*)&h;
}

// ---------------- weight conversion to fp16 ----------------
__global__ void round4_k(const float* __restrict__ in, __half* __restrict__ out, int n4) {
    int i = blockIdx.x * 256 + threadIdx.x;
    if (i >= n4) return;
    float4 v = ((const float4*)in)[i];
    ((uint2*)out)[i] = make_uint2(pack2(v.x, v.y), pack2(v.z, v.w));
}

__global__ void round_layer_k(const float* __restrict__ qw, const float* __restrict__ kw,
                              const float* __restrict__ vw, const float* __restrict__ pw,
                              const float* __restrict__ f1, const float* __restrict__ f2,
                              __half* __restrict__ out) {
    int i = blockIdx.x * 256 + threadIdx.x;      // float4 index, total 3*2^20
    if (i >= 3 * MEG) return;
    int u = i >> 18;
    const float* src;
    int base;
    if (u < 4) {
        src = (u == 0) ? qw : (u == 1) ? kw : (u == 2) ? vw : pw;
        base = i & 262143;
    } else if (u < 8) { src = f1; base = i - 4 * 262144; }
    else             { src = f2; base = i - 8 * 262144; }
    float4 v = ((const float4*)src)[base];
    ((uint2*)out)[i] = make_uint2(pack2(v.x, v.y), pack2(v.z, v.w));
}

// ---------------- im2col (stores fp16) ----------------
__global__ void im2col_k(const float* __restrict__ px, __half* __restrict__ col) {
    int idx = blockIdx.x * 256 + threadIdx.x;
    if (idx >= ROWS * PATCH_K) return;
    int m = idx / PATCH_K;
    int j = idx - m * PATCH_K;
    int c  = j >> 9;
    int r  = j & 511;
    int t  = r >> 8;
    int ph = (r >> 4) & 15;
    int pw = r & 15;
    int b = m / NTOK;
    int n = m - b * NTOK;
    int d  = n / 196;
    int rr = n - d * 196;
    int hy = rr / 14;
    int wx = rr - hy * 14;
    size_t src = ((size_t)((b * 16 + d * 2 + t) * 3 + c)) * (224 * 224)
               + (size_t)(hy * 16 + ph) * 224 + (wx * 16 + pw);
    col[idx] = __float2half_rn(px[src]);
}

// ---------------- fp16 tensor-core GEMM (m16n8k16, fp32 accum) ----------------
// MODE 0: bias, 1: bias+gelu -> half out, 2: bias+residual, 3: fused QKV
__device__ __forceinline__ void mma16(float* c, uint32_t a0, uint32_t a1, uint32_t a2,
                                      uint32_t a3, uint32_t b0, uint32_t b1) {
    asm volatile(
        "mma.sync.aligned.m16n8k16.row.col.f32.f16.f16.f32 "
        "{%0,%1,%2,%3},{%4,%5,%6,%7},{%8,%9},{%0,%1,%2,%3};"
        : "+f"(c[0]), "+f"(c[1]), "+f"(c[2]), "+f"(c[3])
        : "r"(a0), "r"(a1), "r"(a2), "r"(a3), "r"(b0), "r"(b1));
}

#define GRP_PAIRS 513
#define BUF_U32   (4 * GRP_PAIRS * 2)        // 4104
#define DBUF_U32  (2 * BUF_U32)              // A+B per stage: 8208
#define GEMM_SMEM (2 * DBUF_U32 * 4)         // bytes: 65664

template <int MODE>
__global__ __launch_bounds__(256, 2) void tgemm(
    const __half* __restrict__ A,
    const __half* __restrict__ B0, const __half* __restrict__ B1, const __half* __restrict__ B2,
    const float* __restrict__ bias0, const float* __restrict__ bias1, const float* __restrict__ bias2,
    const float* __restrict__ res, float* __restrict__ C0, float* __restrict__ C1,
    float* __restrict__ C2, int M, int N, int K)
{
    extern __shared__ uint32_t smu[];
    int m0 = blockIdx.y * 128;
    int n0 = blockIdx.x * 128;
    const __half* B = B0;
    const float* bias = bias0;
    float* C = C0;
    if (MODE == 3) {
        int ws = n0 >> 10;
        if (ws == 1) { B = B1; bias = bias1; C = C1; }
        else if (ws == 2) { B = B2; bias = bias2; C = C2; }
        n0 &= 1023;
    }

    const int t = threadIdx.x;
    const int quad = t & 7;          // which uint4 (8 halves) of the 64-half chunk
    const int rbase = t >> 3;        // 0..31
    const int g8l = quad >> 1;       // k16-group 0..3
    const int half_s = quad & 1;     // lo/hi slot of pair
    const int warp = t >> 5, lane = t & 31;
    const int wm = (warp >> 2) * 64, wn = (warp & 3) * 32;
    const int g = lane >> 2, tig = lane & 3;

    float acc[4][4][4];
#pragma unroll
    for (int i = 0; i < 4; i++)
#pragma unroll
        for (int j = 0; j < 4; j++)
#pragma unroll
            for (int q = 0; q < 4; q++) acc[i][j][q] = 0.f;

    const int NC = K >> 6;           // 64 halves per chunk

    // prologue: stage chunk 0
    {
        uint32_t* da = smu + g8l * (GRP_PAIRS * 2) + half_s;
        uint32_t* db = da + BUF_U32;
#pragma unroll
        for (int p = 0; p < 4; p++) {
            int gm = m0 + p * 32 + rbase;
            uint4 va = (gm < M) ? *(const uint4*)&A[(size_t)gm * K + quad * 8]
                                : make_uint4(0u, 0u, 0u, 0u);
            uint32_t* d = da + (p * 32 + rbase) * 8;
            d[0] = va.x; d[2] = va.y; d[4] = va.z; d[6] = va.w;
            int gn = n0 + p * 32 + rbase;
            uint4 vb = *(const uint4*)&B[(size_t)gn * K + quad * 8];
            uint32_t* e = db + (p * 32 + rbase) * 8;
            e[0] = vb.x; e[2] = vb.y; e[4] = vb.z; e[6] = vb.w;
        }
    }
    __syncthreads();

    for (int c = 0; c < NC; c++) {
        const uint32_t* a = smu + (c & 1) * DBUF_U32;
        const uint32_t* bsh = a + BUF_U32;
        bool more = (c + 1 < NC);
        int k0n = (c + 1) << 6;
        uint32_t* da = smu + ((c + 1) & 1) * DBUF_U32 + g8l * (GRP_PAIRS * 2) + half_s;
        uint32_t* db = da + BUF_U32;

        auto comp = [&](int gg) {
            uint2 pa[4][2];
            uint2 pb[4];
#pragma unroll
            for (int fm = 0; fm < 4; fm++) {
                int r = wm + fm * 16 + g;
                pa[fm][0] = *(const uint2*)&a[(gg * GRP_PAIRS + r * 4 + tig) * 2];
                pa[fm][1] = *(const uint2*)&a[(gg * GRP_PAIRS + (r + 8) * 4 + tig) * 2];
            }
#pragma unroll
            for (int fn = 0; fn < 4; fn++) {
                int ci = wn + fn * 8 + g;
                pb[fn] = *(const uint2*)&bsh[(gg * GRP_PAIRS + ci * 4 + tig) * 2];
            }
#pragma unroll
            for (int fm = 0; fm < 4; fm++)
#pragma unroll
                for (int fn = 0; fn < 4; fn++)
                    mma16(acc[fm][fn], pa[fm][0].x, pa[fm][1].x, pa[fm][0].y, pa[fm][1].y,
                          pb[fn].x, pb[fn].y);
        };
        auto lda = [&](int p) -> uint4 {
            int gm = m0 + p * 32 + rbase;
            return (gm < M) ? *(const uint4*)&A[(size_t)gm * K + k0n + quad * 8]
                            : make_uint4(0u, 0u, 0u, 0u);
        };
        auto ldb = [&](int p) -> uint4 {
            int gn = n0 + p * 32 + rbase;
            return *(const uint4*)&B[(size_t)gn * K + k0n + quad * 8];
        };
        auto sta = [&](uint4 v, int p) {
            uint32_t* d = da + (p * 32 + rbase) * 8;
            d[0] = v.x; d[2] = v.y; d[4] = v.z; d[6] = v.w;
        };
        auto stb = [&](uint4 v, int p) {
            uint32_t* d = db + (p * 32 + rbase) * 8;
            d[0] = v.x; d[2] = v.y; d[4] = v.z; d[6] = v.w;
        };

        uint4 ra0, ra1, rb0, rb1;
        comp(0);
        if (more) { ra0 = lda(0); ra1 = lda(1); rb0 = ldb(0); rb1 = ldb(1); }
        comp(1);
        if (more) {
            sta(ra0, 0); sta(ra1, 1); stb(rb0, 0); stb(rb1, 1);
            ra0 = lda(2); ra1 = lda(3); rb0 = ldb(2); rb1 = ldb(3);
        }
        comp(2);
        if (more) { sta(ra0, 2); sta(ra1, 3); stb(rb0, 2); stb(rb1, 3); }
        comp(3);
        __syncthreads();
    }

    // epilogue
    __half* Ch = (__half*)C;
#pragma unroll
    for (int fm = 0; fm < 4; fm++) {
        int r0 = m0 + wm + fm * 16 + g;
#pragma unroll
        for (int fn = 0; fn < 4; fn++) {
            int col = n0 + wn + fn * 8 + 2 * tig;
            float b0v = bias[col], b1v = bias[col + 1];
#pragma unroll
            for (int hrow = 0; hrow < 2; hrow++) {
                int r = r0 + hrow * 8;
                if (r >= M) continue;
                float v0 = acc[fm][fn][hrow * 2 + 0] + b0v;
                float v1 = acc[fm][fn][hrow * 2 + 1] + b1v;
                if (MODE == 1) {
                    v0 = 0.5f * v0 * (1.f + erff(v0 * 0.70710678118654752f));
                    v1 = 0.5f * v1 * (1.f + erff(v1 * 0.70710678118654752f));
                    *(uint32_t*)&Ch[(size_t)r * N + col] = pack2(v0, v1);
                } else {
                    if (MODE == 2) {
                        const float* rr = &res[(size_t)r * N + col];
                        v0 += rr[0]; v1 += rr[1];
                    }
                    *(float2*)&C[(size_t)r * N + col] = make_float2(v0, v1);
                }
            }
        }
    }
}

// ---------------- LayerNorm (HALF_OUT: write fp16 for GEMM input) ----------------
template <bool HALF_OUT>
__global__ __launch_bounds__(256) void ln_k(
    const float* __restrict__ x, const float* __restrict__ g,
    const float* __restrict__ b, void* __restrict__ yv)
{
    __shared__ float red[8];
    __shared__ float stat[2];
    int row = blockIdx.x, tid = threadIdx.x;
    const float* xr = x + (size_t)row * HIDDEN;
    float v[4];
    float s = 0.f;
#pragma unroll
    for (int i = 0; i < 4; i++) { v[i] = xr[tid + i * 256]; s += v[i]; }
#pragma unroll
    for (int o = 16; o > 0; o >>= 1) s += __shfl_xor_sync(~0u, s, o);
    if ((tid & 31) == 0) red[tid >> 5] = s;
    __syncthreads();
    if (tid < 32) {
        float t = (tid < 8) ? red[tid] : 0.f;
#pragma unroll
        for (int o = 4; o > 0; o >>= 1) t += __shfl_xor_sync(~0u, t, o);
        if (tid == 0) stat[0] = t * (1.f / HIDDEN);
    }
    __syncthreads();
    float mu = stat[0];
    float s2 = 0.f;
#pragma unroll
    for (int i = 0; i < 4; i++) { float d = v[i] - mu; s2 += d * d; }
#pragma unroll
    for (int o = 16; o > 0; o >>= 1) s2 += __shfl_xor_sync(~0u, s2, o);
    if ((tid & 31) == 0) red[tid >> 5] = s2;
    __syncthreads();
    if (tid < 32) {
        float t = (tid < 8) ? red[tid] : 0.f;
#pragma unroll
        for (int o = 4; o > 0; o >>= 1) t += __shfl_xor_sync(~0u, t, o);
        if (tid == 0) stat[1] = rsqrtf(t * (1.f / HIDDEN) + 1e-6f);
    }
    __syncthreads();
    float rs = stat[1];
#pragma unroll
    for (int i = 0; i < 4; i++) {
        int c = tid + i * 256;
        float o = (v[i] - mu) * rs * g[c] + b[c];
        if (HALF_OUT) ((__half*)yv)[(size_t)row * HIDDEN + c] = __float2half_rn(o);
        else          ((float*)yv)[(size_t)row * HIDDEN + c] = o;
    }
}

// ---------------- RoPE ----------------
__global__ void rope_k(float* __restrict__ q, float* __restrict__ k) {
    int idx = blockIdx.x * 256 + threadIdx.x;
    const int TOTAL = ROWS * HEADS * 30;
    if (idx >= TOTAL) return;
    int pair = idx % 30;
    int t = idx / 30;
    int h = t & 15;
    int bn = t >> 4;
    int n = bn % NTOK;
    int a = pair / 10, i = pair - a * 10;
    int dpos = n / 196, r = n - dpos * 196;
    int pos = (a == 0) ? dpos : (a == 1) ? (r / 14) : (r % 14);
    int i0 = (2 * i) % 10, i1 = (2 * i + 1) % 10;
    const float LN1E4_O10 = 0.92103403719761840f;
    float f0 = (float)pos * expf(-LN1E4_O10 * (float)i0);
    float f1 = (float)pos * expf(-LN1E4_O10 * (float)i1);
    float s0, c0, s1, c1;
    sincosf(f0, &s0, &c0);
    sincosf(f1, &s1, &c1);
    size_t base = (size_t)bn * HIDDEN + h * HEADD + a * 20 + 2 * i;
    float q0 = q[base], q1 = q[base + 1];
    q[base]     = q0 * c0 - q1 * s0;
    q[base + 1] = q1 * c1 + q0 * s1;
    float k0 = k[base], k1 = k[base + 1];
    k[base]     = k0 * c0 - k1 * s0;
    k[base + 1] = k1 * c1 + k0 * s1;
}

// ---------------- Flash attention via mma.sync tf32 (fp32 in, fp16 out) ----------
__device__ __forceinline__ void mma8(float* c, uint32_t a0, uint32_t a1, uint32_t a2,
                                     uint32_t a3, uint32_t b0, uint32_t b1) {
    asm volatile(
        "mma.sync.aligned.m16n8k8.row.col.f32.tf32.tf32.f32 "
        "{%0,%1,%2,%3},{%4,%5,%6,%7},{%8,%9},{%0,%1,%2,%3};"
        : "+f"(c[0]), "+f"(c[1]), "+f"(c[2]), "+f"(c[3])
        : "r"(a0), "r"(a1), "r"(a2), "r"(a3), "r"(b0), "r"(b1));
}
#define KST 68
#define VST 72
#define PST 68
#define ATTN_SMEM ((64 * KST + 64 * VST + 64 * PST) * 4)

__global__ __launch_bounds__(128) void attn_mma(
    const float* __restrict__ Q, const float* __restrict__ K,
    const float* __restrict__ V, __half* __restrict__ O)
{
    extern __shared__ uint32_t smem[];
    uint32_t* Ks = smem;
    uint32_t* Vs = Ks + 64 * KST;
    uint32_t* Ps = Vs + 64 * VST;

    int b = blockIdx.y >> 4, h = blockIdx.y & 15;
    int q0 = blockIdx.x * 64;
    int tid = threadIdx.x, w = tid >> 5, lane = tid & 31;
    int g = lane >> 2, tq = lane & 3;

    const float* Qb = Q + (size_t)b * NTOK * HIDDEN + h * HEADD;
    const float* Kb = K + (size_t)b * NTOK * HIDDEN + h * HEADD;
    const float* Vb = V + (size_t)b * NTOK * HIDDEN + h * HEADD;

    uint32_t qa[8][4];
    int qrow0 = q0 + w * 16 + g;
    int qrow1 = qrow0 + 8;
    bool qv0 = qrow0 < NTOK, qv1 = qrow1 < NTOK;
    const float* qp0 = Qb + (size_t)qrow0 * HIDDEN;
    const float* qp1 = Qb + (size_t)qrow1 * HIDDEN;
#pragma unroll
    for (int ks = 0; ks < 8; ks++) {
        int d0 = ks * 8 + tq;
        qa[ks][0] = f2tf(qv0 ? qp0[d0] * 0.125f : 0.f);
        qa[ks][1] = f2tf(qv1 ? qp1[d0] * 0.125f : 0.f);
        qa[ks][2] = f2tf(qv0 ? qp0[d0 + 4] * 0.125f : 0.f);
        qa[ks][3] = f2tf(qv1 ? qp1[d0 + 4] * 0.125f : 0.f);
    }

    float oacc[8][4];
#pragma unroll
    for (int i = 0; i < 8; i++)
#pragma unroll
        for (int j = 0; j < 4; j++) oacc[i][j] = 0.f;
    float m0 = -1e30f, m1 = -1e30f, l0 = 0.f, l1 = 0.f;

    uint32_t* pw = Ps + w * 16 * PST;

    for (int kt = 0; kt < 25; kt++) {
        int k0 = kt * 64;
        __syncthreads();
#pragma unroll
        for (int i = 0; i < 8; i++) {
            int e = tid + i * 128;
            int r = e >> 4, c4 = (e & 15) * 4;
            int ki = k0 + r;
            float4 kv, vv;
            if (ki < NTOK) {
                kv = *(const float4*)&Kb[(size_t)ki * HIDDEN + c4];
                vv = *(const float4*)&Vb[(size_t)ki * HIDDEN + c4];
            } else {
                kv = make_float4(0.f, 0.f, 0.f, 0.f);
                vv = kv;
            }
            uint32_t* kd = &Ks[r * KST + c4];
            kd[0] = f2tf(kv.x); kd[1] = f2tf(kv.y); kd[2] = f2tf(kv.z); kd[3] = f2tf(kv.w);
            uint32_t* vd = &Vs[r * VST + c4];
            vd[0] = f2tf(vv.x); vd[1] = f2tf(vv.y); vd[2] = f2tf(vv.z); vd[3] = f2tf(vv.w);
        }
        __syncthreads();

        float sacc[8][4];
#pragma unroll
        for (int nf = 0; nf < 8; nf++) {
            sacc[nf][0] = 0.f; sacc[nf][1] = 0.f; sacc[nf][2] = 0.f; sacc[nf][3] = 0.f;
            const uint32_t* krow = &Ks[(nf * 8 + g) * KST];
#pragma unroll
            for (int ks = 0; ks < 8; ks++) {
                uint32_t b0 = krow[ks * 8 + tq];
                uint32_t b1 = krow[ks * 8 + tq + 4];
                mma8(sacc[nf], qa[ks][0], qa[ks][1], qa[ks][2], qa[ks][3], b0, b1);
            }
        }

        float mx0 = -1e30f, mx1 = -1e30f;
#pragma unroll
        for (int nf = 0; nf < 8; nf++) {
            int col0 = k0 + nf * 8 + 2 * tq;
            if (col0 >= NTOK)     { sacc[nf][0] = -1e30f; sacc[nf][2] = -1e30f; }
            if (col0 + 1 >= NTOK) { sacc[nf][1] = -1e30f; sacc[nf][3] = -1e30f; }
            mx0 = fmaxf(mx0, fmaxf(sacc[nf][0], sacc[nf][1]));
            mx1 = fmaxf(mx1, fmaxf(sacc[nf][2], sacc[nf][3]));
        }
        mx0 = fmaxf(mx0, __shfl_xor_sync(~0u, mx0, 1));
        mx0 = fmaxf(mx0, __shfl_xor_sync(~0u, mx0, 2));
        mx1 = fmaxf(mx1, __shfl_xor_sync(~0u, mx1, 1));
        mx1 = fmaxf(mx1, __shfl_xor_sync(~0u, mx1, 2));
        float mn0 = fmaxf(m0, mx0), mn1 = fmaxf(m1, mx1);
        float corr0 = __expf(m0 - mn0), corr1 = __expf(m1 - mn1);
        m0 = mn0; m1 = mn1;

        float ls0 = 0.f, ls1 = 0.f;
#pragma unroll
        for (int nf = 0; nf < 8; nf++) {
            float p0 = __expf(sacc[nf][0] - mn0);
            float p1 = __expf(sacc[nf][1] - mn0);
            float p2 = __expf(sacc[nf][2] - mn1);
            float p3 = __expf(sacc[nf][3] - mn1);
            ls0 += p0 + p1; ls1 += p2 + p3;
            *(uint2*)&pw[g * PST + nf * 8 + 2 * tq]       = make_uint2(f2tf(p0), f2tf(p1));
            *(uint2*)&pw[(g + 8) * PST + nf * 8 + 2 * tq] = make_uint2(f2tf(p2), f2tf(p3));
        }
        ls0 += __shfl_xor_sync(~0u, ls0, 1);
        ls0 += __shfl_xor_sync(~0u, ls0, 2);
        ls1 += __shfl_xor_sync(~0u, ls1, 1);
        ls1 += __shfl_xor_sync(~0u, ls1, 2);
        l0 = l0 * corr0 + ls0;
        l1 = l1 * corr1 + ls1;
#pragma unroll
        for (int nf2 = 0; nf2 < 8; nf2++) {
            oacc[nf2][0] *= corr0; oacc[nf2][1] *= corr0;
            oacc[nf2][2] *= corr1; oacc[nf2][3] *= corr1;
        }
        __syncwarp();

#pragma unroll
        for (int ks = 0; ks < 8; ks++) {
            uint32_t a0 = pw[g * PST + ks * 8 + tq];
            uint32_t a1 = pw[(g + 8) * PST + ks * 8 + tq];
            uint32_t a2 = pw[g * PST + ks * 8 + tq + 4];
            uint32_t a3 = pw[(g + 8) * PST + ks * 8 + tq + 4];
            const uint32_t* vr0 = &Vs[(ks * 8 + tq) * VST];
            const uint32_t* vr1 = &Vs[(ks * 8 + tq + 4) * VST];
#pragma unroll
            for (int nf2 = 0; nf2 < 8; nf2++) {
                mma8(oacc[nf2], a0, a1, a2, a3, vr0[nf2 * 8 + g], vr1[nf2 * 8 + g]);
            }
        }
        __syncwarp();
    }

    float inv0 = 1.f / l0, inv1 = 1.f / l1;
    __half* Ob = O + (size_t)b * NTOK * HIDDEN + h * HEADD;
#pragma unroll
    for (int nf2 = 0; nf2 < 8; nf2++) {
        int d0 = nf2 * 8 + 2 * tq;
        if (qv0)
            *(uint32_t*)&Ob[(size_t)qrow0 * HIDDEN + d0] =
                pack2(oacc[nf2][0] * inv0, oacc[nf2][1] * inv0);
        if (qv1)
            *(uint32_t*)&Ob[(size_t)qrow1 * HIDDEN + d0] =
                pack2(oacc[nf2][2] * inv1, oacc[nf2][3] * inv1);
    }
}

// ---------------- host orchestration ----------------
extern "C" void kernel_launch(void* const* d_in, const int* in_sizes, int n_in,
                              void* d_out, int out_size) {
    (void)in_sizes; (void)n_in; (void)out_size;
    const float* px      = (const float*)d_in[0];
    const float* patch_w = (const float*)d_in[1];
    const float* patch_b = (const float*)d_in[2];
    const float* ln1g = (const float*)d_in[3];
    const float* ln1b = (const float*)d_in[4];
    const float* qw = (const float*)d_in[5];
    const float* qb = (const float*)d_in[6];
    const float* kw = (const float*)d_in[7];
    const float* kb = (const float*)d_in[8];
    const float* vw = (const float*)d_in[9];
    const float* vb = (const float*)d_in[10];
    const float* pw = (const float*)d_in[11];
    const float* pb = (const float*)d_in[12];
    const float* ln2g = (const float*)d_in[13];
    const float* ln2b = (const float*)d_in[14];
    const float* fc1w = (const float*)d_in[15];
    const float* fc1b = (const float*)d_in[16];
    const float* fc2w = (const float*)d_in[17];
    const float* fc2b = (const float*)d_in[18];
    const float* lnfg = (const float*)d_in[19];
    const float* lnfb = (const float*)d_in[20];
    float* out = (float*)d_out;

    void *ph, *pq, *pk, *pv, *pxnh, *paoh, *pmlph, *pcolh, *pwrh;
    cudaGetSymbolAddress(&ph,  g_h);
    cudaGetSymbolAddress(&pq,  g_q);
    cudaGetSymbolAddress(&pk,  g_k);
    cudaGetSymbolAddress(&pv,  g_v);
    cudaGetSymbolAddress(&pxnh, g_xnh);
    cudaGetSymbolAddress(&paoh, g_aoh);
    cudaGetSymbolAddress(&pmlph, g_mlph);
    cudaGetSymbolAddress(&pcolh, g_colh);
    cudaGetSymbolAddress(&pwrh, g_wrh);
    float*  h    = (float*)ph;
    float*  q    = (float*)pq;
    float*  k    = (float*)pk;
    float*  v    = (float*)pv;
    __half* xnh  = (__half*)pxnh;
    __half* aoh  = (__half*)paoh;
    __half* mlph = (__half*)pmlph;
    __half* colh = (__half*)pcolh;
    __half* wrh  = (__half*)pwrh;

    cudaFuncSetAttribute(attn_mma, cudaFuncAttributeMaxDynamicSharedMemorySize, ATTN_SMEM);
    cudaFuncSetAttribute(tgemm<0>, cudaFuncAttributeMaxDynamicSharedMemorySize, GEMM_SMEM);
    cudaFuncSetAttribute(tgemm<1>, cudaFuncAttributeMaxDynamicSharedMemorySize, GEMM_SMEM);
    cudaFuncSetAttribute(tgemm<2>, cudaFuncAttributeMaxDynamicSharedMemorySize, GEMM_SMEM);
    cudaFuncSetAttribute(tgemm<3>, cudaFuncAttributeMaxDynamicSharedMemorySize, GEMM_SMEM);

    // patch embed
    im2col_k<<<(ROWS * PATCH_K + 255) / 256, 256>>>(px, colh);
    round4_k<<<(HIDDEN * PATCH_K / 4 + 255) / 256, 256>>>(patch_w, wrh, HIDDEN * PATCH_K / 4);
    tgemm<0><<<dim3(HIDDEN / 128, 25), 256, GEMM_SMEM>>>(
        colh, wrh, wrh, wrh, patch_b, patch_b, patch_b,
        nullptr, h, h, h, ROWS, HIDDEN, PATCH_K);

    for (int l = 0; l < LAYERS; l++) {
        size_t wo = (size_t)l * HIDDEN * HIDDEN;
        size_t bo = (size_t)l * HIDDEN;
        round_layer_k<<<(3 * MEG + 255) / 256, 256>>>(
            qw + wo, kw + wo, vw + wo, pw + wo,
            fc1w + (size_t)l * MLPD * HIDDEN, fc2w + (size_t)l * HIDDEN * MLPD, wrh);
        // attention block
        ln_k<true><<<ROWS, 256>>>(h, ln1g + bo, ln1b + bo, xnh);
        tgemm<3><<<dim3(24, 25), 256, GEMM_SMEM>>>(
            xnh, wrh, wrh + MEG, wrh + 2 * MEG, qb + bo, kb + bo, vb + bo,
            nullptr, q, k, v, ROWS, HIDDEN, HIDDEN);
        rope_k<<<(ROWS * HEADS * 30 + 255) / 256, 256>>>(q, k);
        attn_mma<<<dim3(25, BATCH * HEADS), 128, ATTN_SMEM>>>(q, k, v, aoh);
        tgemm<2><<<dim3(8, 25), 256, GEMM_SMEM>>>(
            aoh, wrh + 3 * MEG, wrh, wrh, pb + bo, pb + bo, pb + bo,
            h, h, h, h, ROWS, HIDDEN, HIDDEN);
        // MLP block
        ln_k<true><<<ROWS, 256>>>(h, ln2g + bo, ln2b + bo, xnh);
        tgemm<1><<<dim3(MLPD / 128, 25), 256, GEMM_SMEM>>>(
            xnh, wrh + 4 * MEG, wrh, wrh, fc1b + (size_t)l * MLPD, fc1b, fc1b,
            nullptr, (float*)mlph, (float*)mlph, (float*)mlph, ROWS, MLPD, HIDDEN);
        tgemm<2><<<dim3(8, 25), 256, GEMM_SMEM>>>(
            mlph, wrh + 8 * MEG, wrh, wrh, fc2b + bo, fc2b, fc2b,
            h, h, h, h, ROWS, HIDDEN, MLPD);
    }

    ln_k<false><<<ROWS, 256>>>(h, lnfg, lnfb, out);
}

// round 8
// speedup vs baseline: 6.5382x; 1.1823x over previous
#include <cuda_runtime.h>
#include <cuda_fp16.h>
#include <math.h>
#include <stdint.h>

#define HIDDEN 1024
#define HEADS 16
#define HEADD 64
#define LAYERS 4
#define MLPD 4096
#define NTOK 1568
#define BATCH 2
#define ROWS (BATCH * NTOK)          // 3136
#define PATCH_K 1536                 // 3*2*16*16
#define MEG (1 << 20)

// ---------------- scratch (device globals; no allocation allowed) ----------------
__device__ float  g_h  [ROWS * HIDDEN];
__device__ float  g_q  [ROWS * HIDDEN];
__device__ float  g_k  [ROWS * HIDDEN];
__device__ __half g_qh  [ROWS * HIDDEN];
__device__ __half g_kh  [ROWS * HIDDEN];
__device__ __half g_vh  [ROWS * HIDDEN];
__device__ __half g_xnh [ROWS * HIDDEN];
__device__ __half g_aoh [ROWS * HIDDEN];
__device__ __half g_mlph[ROWS * MLPD];
__device__ __half g_colh[ROWS * PATCH_K];
__device__ __half g_wrh [12 * MEG];   // per-layer fp16 weights (or patch embed)

__device__ __forceinline__ uint32_t pack2(float a, float b) {
    __half2 h = __floats2half2_rn(a, b);
    return *(uint32_t*)&h;
}

// ---------------- weight conversion to fp16 ----------------
__global__ void round4_k(const float* __restrict__ in, __half* __restrict__ out, int n4) {
    int i = blockIdx.x * 256 + threadIdx.x;
    if (i >= n4) return;
    float4 v = ((const float4*)in)[i];
    ((uint2*)out)[i] = make_uint2(pack2(v.x, v.y), pack2(v.z, v.w));
}

__global__ void round_layer_k(const float* __restrict__ qw, const float* __restrict__ kw,
                              const float* __restrict__ vw, const float* __restrict__ pw,
                              const float* __restrict__ f1, const float* __restrict__ f2,
                              __half* __restrict__ out) {
    int i = blockIdx.x * 256 + threadIdx.x;      // float4 index, total 3*2^20
    if (i >= 3 * MEG) return;
    int u = i >> 18;
    const float* src;
    int base;
    if (u < 4) {
        src = (u == 0) ? qw : (u == 1) ? kw : (u == 2) ? vw : pw;
        base = i & 262143;
    } else if (u < 8) { src = f1; base = i - 4 * 262144; }
    else             { src = f2; base = i - 8 * 262144; }
    float4 v = ((const float4*)src)[base];
    ((uint2*)out)[i] = make_uint2(pack2(v.x, v.y), pack2(v.z, v.w));
}

// ---------------- im2col (stores fp16) ----------------
__global__ void im2col_k(const float* __restrict__ px, __half* __restrict__ col) {
    int idx = blockIdx.x * 256 + threadIdx.x;
    if (idx >= ROWS * PATCH_K) return;
    int m = idx / PATCH_K;
    int j = idx - m * PATCH_K;
    int c  = j >> 9;
    int r  = j & 511;
    int t  = r >> 8;
    int ph = (r >> 4) & 15;
    int pw = r & 15;
    int b = m / NTOK;
    int n = m - b * NTOK;
    int d  = n / 196;
    int rr = n - d * 196;
    int hy = rr / 14;
    int wx = rr - hy * 14;
    size_t src = ((size_t)((b * 16 + d * 2 + t) * 3 + c)) * (224 * 224)
               + (size_t)(hy * 16 + ph) * 224 + (wx * 16 + pw);
    col[idx] = __float2half_rn(px[src]);
}

// ---------------- fp16 tensor-core GEMM (m16n8k16, fp32 accum) ----------------
// MODE 0: bias, 1: bias+gelu -> half out, 2: bias+residual, 3: fused QKV (V -> half)
__device__ __forceinline__ void mma16(float* c, uint32_t a0, uint32_t a1, uint32_t a2,
                                      uint32_t a3, uint32_t b0, uint32_t b1) {
    asm volatile(
        "mma.sync.aligned.m16n8k16.row.col.f32.f16.f16.f32 "
        "{%0,%1,%2,%3},{%4,%5,%6,%7},{%8,%9},{%0,%1,%2,%3};"
        : "+f"(c[0]), "+f"(c[1]), "+f"(c[2]), "+f"(c[3])
        : "r"(a0), "r"(a1), "r"(a2), "r"(a3), "r"(b0), "r"(b1));
}

#define GRP_PAIRS 513
#define BUF_U32   (4 * GRP_PAIRS * 2)        // 4104
#define DBUF_U32  (2 * BUF_U32)              // A+B per stage: 8208
#define GEMM_SMEM (2 * DBUF_U32 * 4)         // bytes: 65664

template <int MODE>
__global__ __launch_bounds__(256, 2) void tgemm(
    const __half* __restrict__ A,
    const __half* __restrict__ B0, const __half* __restrict__ B1, const __half* __restrict__ B2,
    const float* __restrict__ bias0, const float* __restrict__ bias1, const float* __restrict__ bias2,
    const float* __restrict__ res, float* __restrict__ C0, float* __restrict__ C1,
    float* __restrict__ C2, int M, int N, int K)
{
    extern __shared__ uint32_t smu[];
    int m0 = blockIdx.y * 128;
    int n0 = blockIdx.x * 128;
    const __half* B = B0;
    const float* bias = bias0;
    float* C = C0;
    int wsel = 0;
    if (MODE == 3) {
        wsel = n0 >> 10;
        if (wsel == 1) { B = B1; bias = bias1; C = C1; }
        else if (wsel == 2) { B = B2; bias = bias2; C = C2; }
        n0 &= 1023;
    }

    const int t = threadIdx.x;
    const int quad = t & 7;
    const int rbase = t >> 3;
    const int g8l = quad >> 1;
    const int half_s = quad & 1;
    const int warp = t >> 5, lane = t & 31;
    const int wm = (warp >> 2) * 64, wn = (warp & 3) * 32;
    const int g = lane >> 2, tig = lane & 3;

    float acc[4][4][4];
#pragma unroll
    for (int i = 0; i < 4; i++)
#pragma unroll
        for (int j = 0; j < 4; j++)
#pragma unroll
            for (int q = 0; q < 4; q++) acc[i][j][q] = 0.f;

    const int NC = K >> 6;           // 64 halves per chunk

    {
        uint32_t* da = smu + g8l * (GRP_PAIRS * 2) + half_s;
        uint32_t* db = da + BUF_U32;
#pragma unroll
        for (int p = 0; p < 4; p++) {
            int gm = m0 + p * 32 + rbase;
            uint4 va = (gm < M) ? *(const uint4*)&A[(size_t)gm * K + quad * 8]
                                : make_uint4(0u, 0u, 0u, 0u);
            uint32_t* d = da + (p * 32 + rbase) * 8;
            d[0] = va.x; d[2] = va.y; d[4] = va.z; d[6] = va.w;
            int gn = n0 + p * 32 + rbase;
            uint4 vb = *(const uint4*)&B[(size_t)gn * K + quad * 8];
            uint32_t* e = db + (p * 32 + rbase) * 8;
            e[0] = vb.x; e[2] = vb.y; e[4] = vb.z; e[6] = vb.w;
        }
    }
    __syncthreads();

    for (int c = 0; c < NC; c++) {
        const uint32_t* a = smu + (c & 1) * DBUF_U32;
        const uint32_t* bsh = a + BUF_U32;
        bool more = (c + 1 < NC);
        int k0n = (c + 1) << 6;
        uint32_t* da = smu + ((c + 1) & 1) * DBUF_U32 + g8l * (GRP_PAIRS * 2) + half_s;
        uint32_t* db = da + BUF_U32;

        auto comp = [&](int gg) {
            uint2 pa[4][2];
            uint2 pb[4];
#pragma unroll
            for (int fm = 0; fm < 4; fm++) {
                int r = wm + fm * 16 + g;
                pa[fm][0] = *(const uint2*)&a[(gg * GRP_PAIRS + r * 4 + tig) * 2];
                pa[fm][1] = *(const uint2*)&a[(gg * GRP_PAIRS + (r + 8) * 4 + tig) * 2];
            }
#pragma unroll
            for (int fn = 0; fn < 4; fn++) {
                int ci = wn + fn * 8 + g;
                pb[fn] = *(const uint2*)&bsh[(gg * GRP_PAIRS + ci * 4 + tig) * 2];
            }
#pragma unroll
            for (int fm = 0; fm < 4; fm++)
#pragma unroll
                for (int fn = 0; fn < 4; fn++)
                    mma16(acc[fm][fn], pa[fm][0].x, pa[fm][1].x, pa[fm][0].y, pa[fm][1].y,
                          pb[fn].x, pb[fn].y);
        };
        auto lda = [&](int p) -> uint4 {
            int gm = m0 + p * 32 + rbase;
            return (gm < M) ? *(const uint4*)&A[(size_t)gm * K + k0n + quad * 8]
                            : make_uint4(0u, 0u, 0u, 0u);
        };
        auto ldb = [&](int p) -> uint4 {
            int gn = n0 + p * 32 + rbase;
            return *(const uint4*)&B[(size_t)gn * K + k0n + quad * 8];
        };
        auto sta = [&](uint4 v, int p) {
            uint32_t* d = da + (p * 32 + rbase) * 8;
            d[0] = v.x; d[2] = v.y; d[4] = v.z; d[6] = v.w;
        };
        auto stb = [&](uint4 v, int p) {
            uint32_t* d = db + (p * 32 + rbase) * 8;
            d[0] = v.x; d[2] = v.y; d[4] = v.z; d[6] = v.w;
        };

        uint4 ra0, ra1, rb0, rb1;
        comp(0);
        if (more) { ra0 = lda(0); ra1 = lda(1); rb0 = ldb(0); rb1 = ldb(1); }
        comp(1);
        if (more) {
            sta(ra0, 0); sta(ra1, 1); stb(rb0, 0); stb(rb1, 1);
            ra0 = lda(2); ra1 = lda(3); rb0 = ldb(2); rb1 = ldb(3);
        }
        comp(2);
        if (more) { sta(ra0, 2); sta(ra1, 3); stb(rb0, 2); stb(rb1, 3); }
        comp(3);
        __syncthreads();
    }

    // epilogue
    __half* Ch = (__half*)C;
    bool hstore = (MODE == 1) || (MODE == 3 && wsel == 2);
#pragma unroll
    for (int fm = 0; fm < 4; fm++) {
        int r0 = m0 + wm + fm * 16 + g;
#pragma unroll
        for (int fn = 0; fn < 4; fn++) {
            int col = n0 + wn + fn * 8 + 2 * tig;
            float b0v = bias[col], b1v = bias[col + 1];
#pragma unroll
            for (int hrow = 0; hrow < 2; hrow++) {
                int r = r0 + hrow * 8;
                if (r >= M) continue;
                float v0 = acc[fm][fn][hrow * 2 + 0] + b0v;
                float v1 = acc[fm][fn][hrow * 2 + 1] + b1v;
                if (MODE == 1) {
                    v0 = 0.5f * v0 * (1.f + erff(v0 * 0.70710678118654752f));
                    v1 = 0.5f * v1 * (1.f + erff(v1 * 0.70710678118654752f));
                }
                if (hstore) {
                    *(uint32_t*)&Ch[(size_t)r * N + col] = pack2(v0, v1);
                } else {
                    if (MODE == 2) {
                        const float* rr = &res[(size_t)r * N + col];
                        v0 += rr[0]; v1 += rr[1];
                    }
                    *(float2*)&C[(size_t)r * N + col] = make_float2(v0, v1);
                }
            }
        }
    }
}

// ---------------- LayerNorm (HALF_OUT: write fp16 for GEMM input) ----------------
template <bool HALF_OUT>
__global__ __launch_bounds__(256) void ln_k(
    const float* __restrict__ x, const float* __restrict__ g,
    const float* __restrict__ b, void* __restrict__ yv)
{
    __shared__ float red[8];
    __shared__ float stat[2];
    int row = blockIdx.x, tid = threadIdx.x;
    const float* xr = x + (size_t)row * HIDDEN;
    float v[4];
    float s = 0.f;
#pragma unroll
    for (int i = 0; i < 4; i++) { v[i] = xr[tid + i * 256]; s += v[i]; }
#pragma unroll
    for (int o = 16; o > 0; o >>= 1) s += __shfl_xor_sync(~0u, s, o);
    if ((tid & 31) == 0) red[tid >> 5] = s;
    __syncthreads();
    if (tid < 32) {
        float t = (tid < 8) ? red[tid] : 0.f;
#pragma unroll
        for (int o = 4; o > 0; o >>= 1) t += __shfl_xor_sync(~0u, t, o);
        if (tid == 0) stat[0] = t * (1.f / HIDDEN);
    }
    __syncthreads();
    float mu = stat[0];
    float s2 = 0.f;
#pragma unroll
    for (int i = 0; i < 4; i++) { float d = v[i] - mu; s2 += d * d; }
#pragma unroll
    for (int o = 16; o > 0; o >>= 1) s2 += __shfl_xor_sync(~0u, s2, o);
    if ((tid & 31) == 0) red[tid >> 5] = s2;
    __syncthreads();
    if (tid < 32) {
        float t = (tid < 8) ? red[tid] : 0.f;
#pragma unroll
        for (int o = 4; o > 0; o >>= 1) t += __shfl_xor_sync(~0u, t, o);
        if (tid == 0) stat[1] = rsqrtf(t * (1.f / HIDDEN) + 1e-6f);
    }
    __syncthreads();
    float rs = stat[1];
#pragma unroll
    for (int i = 0; i < 4; i++) {
        int c = tid + i * 256;
        float o = (v[i] - mu) * rs * g[c] + b[c];
        if (HALF_OUT) ((__half*)yv)[(size_t)row * HIDDEN + c] = __float2half_rn(o);
        else          ((float*)yv)[(size_t)row * HIDDEN + c] = o;
    }
}

// ---------------- RoPE: fp32 q/k in -> fp16 q (pre-scaled 1/8) / k out ----------
__global__ void rope_h(const float* __restrict__ q, const float* __restrict__ k,
                       __half* __restrict__ qh, __half* __restrict__ kh) {
    int idx = blockIdx.x * 256 + threadIdx.x;
    const int TOTAL = ROWS * HEADS * 32;
    if (idx >= TOTAL) return;
    int j = idx & 31;                // pair index within head dim (2*j, 2*j+1)
    int t = idx >> 5;
    int h = t & 15;
    int bn = t >> 4;
    size_t base = (size_t)bn * HIDDEN + h * HEADD + 2 * j;
    float x0 = q[base], x1 = q[base + 1];
    float y0 = k[base], y1 = k[base + 1];
    if (j < 30) {
        int n = bn % NTOK;
        int a = j / 10, i = j - a * 10;
        int dpos = n / 196, r = n - dpos * 196;
        int pos = (a == 0) ? dpos : (a == 1) ? (r / 14) : (r % 14);
        int i0 = (2 * i) % 10, i1 = (2 * i + 1) % 10;
        const float LN1E4_O10 = 0.92103403719761840f;
        float f0 = (float)pos * expf(-LN1E4_O10 * (float)i0);
        float f1 = (float)pos * expf(-LN1E4_O10 * (float)i1);
        float s0, c0, s1, c1;
        sincosf(f0, &s0, &c0);
        sincosf(f1, &s1, &c1);
        float nq0 = x0 * c0 - x1 * s0;
        float nq1 = x1 * c1 + x0 * s1;
        float nk0 = y0 * c0 - y1 * s0;
        float nk1 = y1 * c1 + y0 * s1;
        x0 = nq0; x1 = nq1; y0 = nk0; y1 = nk1;
    }
    *(uint32_t*)&qh[base] = pack2(x0 * 0.125f, x1 * 0.125f);
    *(uint32_t*)&kh[base] = pack2(y0, y1);
}

// ---------------- Flash attention, fp16 m16n8k16 ----------------
// CTA: 64 q x (b,h), 4 warps x 16 q rows. K staged [key][72h]; V staged [key][72h]
// read via ldmatrix.x4.trans; P packed half2 through per-warp smem.
#define KST2 36   // u32 row stride (72 halves); 36 % 32 == 4 -> conflict-free frags
#define VST2 36
#define PST2 36

__global__ __launch_bounds__(128) void attn_h(
    const __half* __restrict__ Q, const __half* __restrict__ K,
    const __half* __restrict__ V, __half* __restrict__ O)
{
    __shared__ uint32_t Ks[64 * KST2];
    __shared__ uint32_t Vs[64 * VST2];
    __shared__ uint32_t Ps[64 * PST2];

    int b = blockIdx.y >> 4, h = blockIdx.y & 15;
    int q0 = blockIdx.x * 64;
    int tid = threadIdx.x, w = tid >> 5, lane = tid & 31;
    int g = lane >> 2, tq = lane & 3;

    const __half* Qb = Q + (size_t)b * NTOK * HIDDEN + h * HEADD;
    const __half* Kb = K + (size_t)b * NTOK * HIDDEN + h * HEADD;
    const __half* Vb = V + (size_t)b * NTOK * HIDDEN + h * HEADD;

    // Q fragments (A operand, 4 k16-groups), already pre-scaled by 1/8
    uint32_t qa[4][4];
    int qrow0 = q0 + w * 16 + g;
    int qrow1 = qrow0 + 8;
    bool qv0 = qrow0 < NTOK, qv1 = qrow1 < NTOK;
    const __half* qp0 = Qb + (size_t)qrow0 * HIDDEN;
    const __half* qp1 = Qb + (size_t)qrow1 * HIDDEN;
#pragma unroll
    for (int ks = 0; ks < 4; ks++) {
        int d0 = ks * 16 + 2 * tq;
        qa[ks][0] = qv0 ? *(const uint32_t*)&qp0[d0] : 0u;
        qa[ks][1] = qv1 ? *(const uint32_t*)&qp1[d0] : 0u;
        qa[ks][2] = qv0 ? *(const uint32_t*)&qp0[d0 + 8] : 0u;
        qa[ks][3] = qv1 ? *(const uint32_t*)&qp1[d0 + 8] : 0u;
    }

    float oacc[8][4];
#pragma unroll
    for (int i = 0; i < 8; i++)
#pragma unroll
        for (int j = 0; j < 4; j++) oacc[i][j] = 0.f;
    float m0 = -1e30f, m1 = -1e30f, l0 = 0.f, l1 = 0.f;

    uint32_t* pw = Ps + w * 16 * PST2;

    // per-thread ldmatrix (x4.trans) source row/col within a 16x16 V tile
    int vrow = (lane & 7) + ((lane >> 3) & 1) * 8;
    int vcol = (lane >> 4) * 8;      // halves
    uint32_t vs_base;
    asm("{ .reg .u64 t; cvta.to.shared.u64 t, %1; cvt.u32.u64 %0, t; }"
        : "=r"(vs_base) : "l"(Vs));
    uint32_t vaddr_t = vs_base + (uint32_t)(vrow * VST2 * 4 + vcol * 2);

    for (int kt = 0; kt < 25; kt++) {
        int k0 = kt * 64;
        __syncthreads();
        // stage K,V tiles (64 keys x 64 halves each)
#pragma unroll
        for (int i = 0; i < 4; i++) {
            int e = tid + i * 128;          // 512 uint4 units
            int r = e >> 3, c = e & 7;
            int ki = k0 + r;
            uint4 kv, vv;
            if (ki < NTOK) {
                kv = *(const uint4*)&Kb[(size_t)ki * HIDDEN + c * 8];
                vv = *(const uint4*)&Vb[(size_t)ki * HIDDEN + c * 8];
            } else {
                kv = make_uint4(0u, 0u, 0u, 0u);
                vv = kv;
            }
            *(uint4*)&Ks[r * KST2 + c * 4] = kv;
            *(uint4*)&Vs[r * VST2 + c * 4] = vv;
        }
        __syncthreads();

        // S = Q.K^T : 8 key-blocks of n8, 4 k16-groups
        float sacc[8][4];
#pragma unroll
        for (int nf = 0; nf < 8; nf++) {
            sacc[nf][0] = 0.f; sacc[nf][1] = 0.f; sacc[nf][2] = 0.f; sacc[nf][3] = 0.f;
            const uint32_t* krow = &Ks[(nf * 8 + g) * KST2];
#pragma unroll
            for (int ks = 0; ks < 4; ks++) {
                uint32_t b0 = krow[ks * 8 + tq];
                uint32_t b1 = krow[ks * 8 + tq + 4];
                mma16(sacc[nf], qa[ks][0], qa[ks][1], qa[ks][2], qa[ks][3], b0, b1);
            }
        }

        // mask + row max
        float mx0 = -1e30f, mx1 = -1e30f;
#pragma unroll
        for (int nf = 0; nf < 8; nf++) {
            int col0 = k0 + nf * 8 + 2 * tq;
            if (col0 >= NTOK)     { sacc[nf][0] = -1e30f; sacc[nf][2] = -1e30f; }
            if (col0 + 1 >= NTOK) { sacc[nf][1] = -1e30f; sacc[nf][3] = -1e30f; }
            mx0 = fmaxf(mx0, fmaxf(sacc[nf][0], sacc[nf][1]));
            mx1 = fmaxf(mx1, fmaxf(sacc[nf][2], sacc[nf][3]));
        }
        mx0 = fmaxf(mx0, __shfl_xor_sync(~0u, mx0, 1));
        mx0 = fmaxf(mx0, __shfl_xor_sync(~0u, mx0, 2));
        mx1 = fmaxf(mx1, __shfl_xor_sync(~0u, mx1, 1));
        mx1 = fmaxf(mx1, __shfl_xor_sync(~0u, mx1, 2));
        float mn0 = fmaxf(m0, mx0), mn1 = fmaxf(m1, mx1);
        float corr0 = __expf(m0 - mn0), corr1 = __expf(m1 - mn1);
        m0 = mn0; m1 = mn1;

        float ls0 = 0.f, ls1 = 0.f;
#pragma unroll
        for (int nf = 0; nf < 8; nf++) {
            float p0 = __expf(sacc[nf][0] - mn0);
            float p1 = __expf(sacc[nf][1] - mn0);
            float p2 = __expf(sacc[nf][2] - mn1);
            float p3 = __expf(sacc[nf][3] - mn1);
            ls0 += p0 + p1; ls1 += p2 + p3;
            pw[g * PST2 + nf * 4 + tq]       = pack2(p0, p1);
            pw[(g + 8) * PST2 + nf * 4 + tq] = pack2(p2, p3);
        }
        ls0 += __shfl_xor_sync(~0u, ls0, 1);
        ls0 += __shfl_xor_sync(~0u, ls0, 2);
        ls1 += __shfl_xor_sync(~0u, ls1, 1);
        ls1 += __shfl_xor_sync(~0u, ls1, 2);
        l0 = l0 * corr0 + ls0;
        l1 = l1 * corr1 + ls1;
#pragma unroll
        for (int nf2 = 0; nf2 < 8; nf2++) {
            oacc[nf2][0] *= corr0; oacc[nf2][1] *= corr0;
            oacc[nf2][2] *= corr1; oacc[nf2][3] *= corr1;
        }
        __syncwarp();

        // O += P.V : 4 k16-groups, V^T fragments via ldmatrix.x4.trans
#pragma unroll
        for (int ks = 0; ks < 4; ks++) {
            uint32_t a0 = pw[g * PST2 + ks * 8 + tq];
            uint32_t a1 = pw[(g + 8) * PST2 + ks * 8 + tq];
            uint32_t a2 = pw[g * PST2 + ks * 8 + tq + 4];
            uint32_t a3 = pw[(g + 8) * PST2 + ks * 8 + tq + 4];
#pragma unroll
            for (int nfp = 0; nfp < 4; nfp++) {
                uint32_t addr = vaddr_t + (uint32_t)(ks * 16 * VST2 * 4 + nfp * 32);
                uint32_t v0, v1, v2, v3;
                asm volatile(
                    "ldmatrix.sync.aligned.m8n8.x4.trans.shared.b16 {%0,%1,%2,%3}, [%4];"
                    : "=r"(v0), "=r"(v1), "=r"(v2), "=r"(v3) : "r"(addr));
                mma16(oacc[nfp * 2],     a0, a1, a2, a3, v0, v1);
                mma16(oacc[nfp * 2 + 1], a0, a1, a2, a3, v2, v3);
            }
        }
        __syncwarp();
    }

    float inv0 = 1.f / l0, inv1 = 1.f / l1;
    __half* Ob = O + (size_t)b * NTOK * HIDDEN + h * HEADD;
#pragma unroll
    for (int nf2 = 0; nf2 < 8; nf2++) {
        int d0 = nf2 * 8 + 2 * tq;
        if (qv0)
            *(uint32_t*)&Ob[(size_t)qrow0 * HIDDEN + d0] =
                pack2(oacc[nf2][0] * inv0, oacc[nf2][1] * inv0);
        if (qv1)
            *(uint32_t*)&Ob[(size_t)qrow1 * HIDDEN + d0] =
                pack2(oacc[nf2][2] * inv1, oacc[nf2][3] * inv1);
    }
}

// ---------------- host orchestration ----------------
extern "C" void kernel_launch(void* const* d_in, const int* in_sizes, int n_in,
                              void* d_out, int out_size) {
    (void)in_sizes; (void)n_in; (void)out_size;
    const float* px      = (const float*)d_in[0];
    const float* patch_w = (const float*)d_in[1];
    const float* patch_b = (const float*)d_in[2];
    const float* ln1g = (const float*)d_in[3];
    const float* ln1b = (const float*)d_in[4];
    const float* qw = (const float*)d_in[5];
    const float* qb = (const float*)d_in[6];
    const float* kw = (const float*)d_in[7];
    const float* kb = (const float*)d_in[8];
    const float* vw = (const float*)d_in[9];
    const float* vb = (const float*)d_in[10];
    const float* pw = (const float*)d_in[11];
    const float* pb = (const float*)d_in[12];
    const float* ln2g = (const float*)d_in[13];
    const float* ln2b = (const float*)d_in[14];
    const float* fc1w = (const float*)d_in[15];
    const float* fc1b = (const float*)d_in[16];
    const float* fc2w = (const float*)d_in[17];
    const float* fc2b = (const float*)d_in[18];
    const float* lnfg = (const float*)d_in[19];
    const float* lnfb = (const float*)d_in[20];
    float* out = (float*)d_out;

    void *ph, *pq, *pk, *pqh, *pkh, *pvh, *pxnh, *paoh, *pmlph, *pcolh, *pwrh;
    cudaGetSymbolAddress(&ph,  g_h);
    cudaGetSymbolAddress(&pq,  g_q);
    cudaGetSymbolAddress(&pk,  g_k);
    cudaGetSymbolAddress(&pqh, g_qh);
    cudaGetSymbolAddress(&pkh, g_kh);
    cudaGetSymbolAddress(&pvh, g_vh);
    cudaGetSymbolAddress(&pxnh, g_xnh);
    cudaGetSymbolAddress(&paoh, g_aoh);
    cudaGetSymbolAddress(&pmlph, g_mlph);
    cudaGetSymbolAddress(&pcolh, g_colh);
    cudaGetSymbolAddress(&pwrh, g_wrh);
    float*  h    = (float*)ph;
    float*  q    = (float*)pq;
    float*  k    = (float*)pk;
    __half* qh   = (__half*)pqh;
    __half* kh   = (__half*)pkh;
    __half* vh   = (__half*)pvh;
    __half* xnh  = (__half*)pxnh;
    __half* aoh  = (__half*)paoh;
    __half* mlph = (__half*)pmlph;
    __half* colh = (__half*)pcolh;
    __half* wrh  = (__half*)pwrh;

    cudaFuncSetAttribute(tgemm<0>, cudaFuncAttributeMaxDynamicSharedMemorySize, GEMM_SMEM);
    cudaFuncSetAttribute(tgemm<1>, cudaFuncAttributeMaxDynamicSharedMemorySize, GEMM_SMEM);
    cudaFuncSetAttribute(tgemm<2>, cudaFuncAttributeMaxDynamicSharedMemorySize, GEMM_SMEM);
    cudaFuncSetAttribute(tgemm<3>, cudaFuncAttributeMaxDynamicSharedMemorySize, GEMM_SMEM);

    // patch embed
    im2col_k<<<(ROWS * PATCH_K + 255) / 256, 256>>>(px, colh);
    round4_k<<<(HIDDEN * PATCH_K / 4 + 255) / 256, 256>>>(patch_w, wrh, HIDDEN * PATCH_K / 4);
    tgemm<0><<<dim3(HIDDEN / 128, 25), 256, GEMM_SMEM>>>(
        colh, wrh, wrh, wrh, patch_b, patch_b, patch_b,
        nullptr, h, h, h, ROWS, HIDDEN, PATCH_K);

    for (int l = 0; l < LAYERS; l++) {
        size_t wo = (size_t)l * HIDDEN * HIDDEN;
        size_t bo = (size_t)l * HIDDEN;
        round_layer_k<<<(3 * MEG + 255) / 256, 256>>>(
            qw + wo, kw + wo, vw + wo, pw + wo,
            fc1w + (size_t)l * MLPD * HIDDEN, fc2w + (size_t)l * HIDDEN * MLPD, wrh);
        // attention block
        ln_k<true><<<ROWS, 256>>>(h, ln1g + bo, ln1b + bo, xnh);
        tgemm<3><<<dim3(24, 25), 256, GEMM_SMEM>>>(
            xnh, wrh, wrh + MEG, wrh + 2 * MEG, qb + bo, kb + bo, vb + bo,
            nullptr, q, k, (float*)vh, ROWS, HIDDEN, HIDDEN);
        rope_h<<<(ROWS * HEADS * 32 + 255) / 256, 256>>>(q, k, qh, kh);
        attn_h<<<dim3(25, BATCH * HEADS), 128>>>(qh, kh, vh, aoh);
        tgemm<2><<<dim3(8, 25), 256, GEMM_SMEM>>>(
            aoh, wrh + 3 * MEG, wrh, wrh, pb + bo, pb + bo, pb + bo,
            h, h, h, h, ROWS, HIDDEN, HIDDEN);
        // MLP block
        ln_k<true><<<ROWS, 256>>>(h, ln2g + bo, ln2b + bo, xnh);
        tgemm<1><<<dim3(MLPD / 128, 25), 256, GEMM_SMEM>>>(
            xnh, wrh + 4 * MEG, wrh, wrh, fc1b + (size_t)l * MLPD, fc1b, fc1b,
            nullptr, (float*)mlph, (float*)mlph, (float*)mlph, ROWS, MLPD, HIDDEN);
        tgemm<2><<<dim3(8, 25), 256, GEMM_SMEM>>>(
            mlph, wrh + 8 * MEG, wrh, wrh, fc2b + bo, fc2b, fc2b,
            h, h, h, h, ROWS, HIDDEN, MLPD);
    }

    ln_k<false><<<ROWS, 256>>>(h, lnfg, lnfb, out);
}